// round 1
// baseline (speedup 1.0000x reference)
#include <cuda_runtime.h>
#include <cuda_bf16.h>

// Problem constants (fixed by the dataset shapes)
#define BB   32
#define TT   4096
#define HH   16
#define DHH  64
#define DD   1024
#define NKV  4097          // T_CTX + 1 (new token appended)
#define NBH  (BB*HH)       // 512
#define NQ   (BB*HH*DHH)   // 32768

// Scratch (device globals; no allocation allowed)
__device__ float g_qp[8][NQ];
__device__ float g_kp[8][NQ];
__device__ float g_vp[8][NQ];
__device__ float g_q [NQ];
__device__ float g_kn[NQ];
__device__ float g_vn[NQ];
__device__ float g_ctx[NQ];
__device__ float g_op[8][NQ];

__device__ __forceinline__ float2 ldf2(const float* p) {
    return *reinterpret_cast<const float2*>(p);
}

// ---------------------------------------------------------------------------
// Kernel 1: QKV projection partials.
// grid (H=16, DS=8). Block (h, ds) handles d-slice [ds*128, ds*128+128).
// Thread owns dh = tid&63, b-group bg = tid>>6 (8 batches each), all 3 mats.
// Each W matrix element is read exactly once chip-wide.
// ---------------------------------------------------------------------------
__global__ void __launch_bounds__(256) qkv_partial(
    const float* __restrict__ x,
    const float* __restrict__ Wq, const float* __restrict__ Wk,
    const float* __restrict__ Wv)
{
    const int h  = blockIdx.x;
    const int ds = blockIdx.y;
    const int tid = threadIdx.x;

    __shared__ float xs[BB][128];
    for (int i = tid; i < BB*128; i += 256) {
        int bb = i >> 7, dd = i & 127;
        xs[bb][dd] = x[bb*DD + ds*128 + dd];
    }
    __syncthreads();

    const int dh = tid & 63;
    const int bg = tid >> 6;          // 0..3
    const int wcol = h*DHH + dh;      // column in (H*DH)=1024

    float aq[8], ak[8], av[8];
#pragma unroll
    for (int j = 0; j < 8; j++) { aq[j]=0.f; ak[j]=0.f; av[j]=0.f; }

    const float* wqp = Wq + (size_t)(ds*128)*1024 + wcol;
    const float* wkp = Wk + (size_t)(ds*128)*1024 + wcol;
    const float* wvp = Wv + (size_t)(ds*128)*1024 + wcol;

#pragma unroll 4
    for (int d = 0; d < 128; d++) {
        float wq_ = wqp[(size_t)d*1024];
        float wk_ = wkp[(size_t)d*1024];
        float wv_ = wvp[(size_t)d*1024];
#pragma unroll
        for (int j = 0; j < 8; j++) {
            float xv = xs[bg*8 + j][d];   // broadcast within warp
            aq[j] += wq_ * xv;
            ak[j] += wk_ * xv;
            av[j] += wv_ * xv;
        }
    }
#pragma unroll
    for (int j = 0; j < 8; j++) {
        int b = bg*8 + j;
        int o = (b*HH + h)*DHH + dh;
        g_qp[ds][o] = aq[j];
        g_kp[ds][o] = ak[j];
        g_vp[ds][o] = av[j];
    }
}

__global__ void __launch_bounds__(256) qkv_reduce(
    const float* __restrict__ bq, const float* __restrict__ bk,
    const float* __restrict__ bv)
{
    int i = blockIdx.x * 256 + threadIdx.x;   // 0..NQ-1
    int bi = i & 1023;                        // h*64+dh
    float sq = bq[bi], sk = bk[bi], sv = bv[bi];
#pragma unroll
    for (int j = 0; j < 8; j++) {
        sq += g_qp[j][i];
        sk += g_kp[j][i];
        sv += g_vp[j][i];
    }
    g_q[i] = sq; g_kn[i] = sk; g_vn[i] = sv;
}

// ---------------------------------------------------------------------------
// Kernel 2: attention (the HBM-bound part). grid = B*H = 512, 256 threads.
// Phase A: scores (warp-per-row, float2/lane, 4x t-unroll)
// Phase B: block softmax
// Phase C: weighted V sum (warp-strided t, float2/lane accumulators)
// ---------------------------------------------------------------------------
__global__ void __launch_bounds__(256) attn_kernel(
    const float* __restrict__ K, const float* __restrict__ V)
{
    const int bh   = blockIdx.x;
    const int b    = bh >> 4;
    const int h    = bh & 15;
    const int tid  = threadIdx.x;
    const int w    = tid >> 5;
    const int lane = tid & 31;
    const float scale = 0.125f;   // 1/sqrt(64)

    __shared__ float q_s[DHH];
    __shared__ float sc[NKV + 3];
    __shared__ float redm[8];
    __shared__ float reds[8];
    __shared__ float vred[8][DHH];

    if (tid < DHH) q_s[tid] = g_q[bh*DHH + tid];
    __syncthreads();

    const float2 qv = make_float2(q_s[2*lane], q_s[2*lane + 1]);
    const float* kb = K + ((size_t)b*TT*HH + h)*DHH;   // row t at +t*1024

    // t = 4096 (new token) by warp 0
    if (w == 0) {
        float2 kn = ldf2(&g_kn[bh*DHH + 2*lane]);
        float p = kn.x*qv.x + kn.y*qv.y;
#pragma unroll
        for (int o = 16; o; o >>= 1) p += __shfl_xor_sync(0xffffffffu, p, o);
        if (lane == 0) sc[TT] = p * scale;
    }

    // main score loop: each warp handles t = i + w, 4 unrolled per iter
    for (int i = 0; i < TT; i += 32) {
        int t = i + w;
        float2 k0 = ldf2(kb + (size_t)(t      )*1024 + 2*lane);
        float2 k1 = ldf2(kb + (size_t)(t +  8 )*1024 + 2*lane);
        float2 k2 = ldf2(kb + (size_t)(t + 16 )*1024 + 2*lane);
        float2 k3 = ldf2(kb + (size_t)(t + 24 )*1024 + 2*lane);
        float d0 = k0.x*qv.x + k0.y*qv.y;
        float d1 = k1.x*qv.x + k1.y*qv.y;
        float d2 = k2.x*qv.x + k2.y*qv.y;
        float d3 = k3.x*qv.x + k3.y*qv.y;
#pragma unroll
        for (int o = 16; o; o >>= 1) {
            d0 += __shfl_xor_sync(0xffffffffu, d0, o);
            d1 += __shfl_xor_sync(0xffffffffu, d1, o);
            d2 += __shfl_xor_sync(0xffffffffu, d2, o);
            d3 += __shfl_xor_sync(0xffffffffu, d3, o);
        }
        if (lane == 0) {
            sc[t]      = d0 * scale;
            sc[t +  8] = d1 * scale;
            sc[t + 16] = d2 * scale;
            sc[t + 24] = d3 * scale;
        }
    }
    __syncthreads();

    // softmax: block max
    float lm = -1e30f;
    for (int i = tid; i < NKV; i += 256) lm = fmaxf(lm, sc[i]);
#pragma unroll
    for (int o = 16; o; o >>= 1) lm = fmaxf(lm, __shfl_xor_sync(0xffffffffu, lm, o));
    if (lane == 0) redm[w] = lm;
    __syncthreads();
    float m = redm[0];
#pragma unroll
    for (int j = 1; j < 8; j++) m = fmaxf(m, redm[j]);

    // exp + block sum
    float ls = 0.f;
    for (int i = tid; i < NKV; i += 256) {
        float e = __expf(sc[i] - m);
        sc[i] = e;
        ls += e;
    }
#pragma unroll
    for (int o = 16; o; o >>= 1) ls += __shfl_xor_sync(0xffffffffu, ls, o);
    if (lane == 0) reds[w] = ls;
    __syncthreads();   // covers sc[] exp writes AND reds[]
    float denom = 0.f;
#pragma unroll
    for (int j = 0; j < 8; j++) denom += reds[j];
    const float inv = 1.0f / denom;

    // phase C: V accumulation, lane owns dh = {2*lane, 2*lane+1}
    const float* vb = V + ((size_t)b*TT*HH + h)*DHH;
    float ax = 0.f, ay = 0.f;
    for (int i = 0; i < TT; i += 32) {
        int t = i + w;
        float2 v0 = ldf2(vb + (size_t)(t      )*1024 + 2*lane);
        float2 v1 = ldf2(vb + (size_t)(t +  8 )*1024 + 2*lane);
        float2 v2 = ldf2(vb + (size_t)(t + 16 )*1024 + 2*lane);
        float2 v3 = ldf2(vb + (size_t)(t + 24 )*1024 + 2*lane);
        float p0 = sc[t], p1 = sc[t + 8], p2 = sc[t + 16], p3 = sc[t + 24];
        ax += p0*v0.x; ay += p0*v0.y;
        ax += p1*v1.x; ay += p1*v1.y;
        ax += p2*v2.x; ay += p2*v2.y;
        ax += p3*v3.x; ay += p3*v3.y;
    }
    if (w == 0) {
        float p = sc[TT];
        ax += p * g_vn[bh*DHH + 2*lane];
        ay += p * g_vn[bh*DHH + 2*lane + 1];
    }
    vred[w][2*lane]     = ax;
    vred[w][2*lane + 1] = ay;
    __syncthreads();
    if (tid < DHH) {
        float s2 = 0.f;
#pragma unroll
        for (int j = 0; j < 8; j++) s2 += vred[j][tid];
        g_ctx[bh*DHH + tid] = s2 * inv;
    }
}

// ---------------------------------------------------------------------------
// Kernel 3: output projection. Wo read exactly once chip-wide.
// grid (MC=16, KS=8). Thread owns m = mc*64 + (tid&63) and 8 batches.
// ---------------------------------------------------------------------------
__global__ void __launch_bounds__(256) out_partial(const float* __restrict__ Wo)
{
    const int mc = blockIdx.x;
    const int ks = blockIdx.y;
    const int tid = threadIdx.x;

    __shared__ float cs[BB][128];
    for (int i = tid; i < BB*128; i += 256) {
        int bb = i >> 7, kk = i & 127;
        cs[bb][kk] = g_ctx[bb*DD + ks*128 + kk];
    }
    __syncthreads();

    const int m  = mc*64 + (tid & 63);
    const int bg = tid >> 6;

    float acc[8];
#pragma unroll
    for (int j = 0; j < 8; j++) acc[j] = 0.f;

    const float* wp = Wo + (size_t)(ks*128)*1024 + m;
#pragma unroll 4
    for (int k = 0; k < 128; k++) {
        float w_ = wp[(size_t)k*1024];
#pragma unroll
        for (int j = 0; j < 8; j++)
            acc[j] += cs[bg*8 + j][k] * w_;
    }
#pragma unroll
    for (int j = 0; j < 8; j++)
        g_op[ks][(bg*8 + j)*DD + m] = acc[j];
}

__global__ void __launch_bounds__(256) out_reduce(
    const float* __restrict__ bo, float* __restrict__ out)
{
    int i = blockIdx.x * 256 + threadIdx.x;   // b*1024 + m
    float s = bo[i & 1023];
#pragma unroll
    for (int j = 0; j < 8; j++) s += g_op[j][i];
    out[i] = s;
}

// ---------------------------------------------------------------------------
extern "C" void kernel_launch(void* const* d_in, const int* in_sizes, int n_in,
                              void* d_out, int out_size)
{
    const float* x     = (const float*)d_in[0];
    const float* ext_k = (const float*)d_in[1];
    const float* ext_v = (const float*)d_in[2];
    const float* Wq    = (const float*)d_in[3];
    const float* bq    = (const float*)d_in[4];
    const float* Wk    = (const float*)d_in[5];
    const float* bk    = (const float*)d_in[6];
    const float* Wv    = (const float*)d_in[7];
    const float* bv    = (const float*)d_in[8];
    const float* Wo    = (const float*)d_in[9];
    const float* bo    = (const float*)d_in[10];
    // d_in[11] = q_pos (fixed at 4096 by the dataset shapes)

    float* out = (float*)d_out;

    qkv_partial<<<dim3(HH, 8), 256>>>(x, Wq, Wk, Wv);
    qkv_reduce<<<NQ/256, 256>>>(bq, bk, bv);
    attn_kernel<<<NBH, 256>>>(ext_k, ext_v);
    out_partial<<<dim3(16, 8), 256>>>(Wo);
    out_reduce<<<NQ/256, 256>>>(bo, out);
}

// round 2
// speedup vs baseline: 1.1345x; 1.1345x over previous
#include <cuda_runtime.h>
#include <cuda_bf16.h>

// Problem constants (fixed by the dataset shapes)
#define BB   32
#define TT   4096
#define HH   16
#define DHH  64
#define DD   1024
#define NKV  4097          // T_CTX + 1 (new token appended)
#define NBH  (BB*HH)       // 512
#define NQ   (BB*HH*DHH)   // 32768
#define NSL  32            // split-K slices for projections

// Scratch (device globals; no allocation allowed)
__device__ float g_qp[NSL][NQ];
__device__ float g_kp[NSL][NQ];
__device__ float g_vp[NSL][NQ];
__device__ float g_ctx[NQ];
__device__ float g_op[NSL][NQ];

__device__ __forceinline__ float2 ldf2(const float* p) {
    return *reinterpret_cast<const float2*>(p);
}

// ---------------------------------------------------------------------------
// Kernel 1: QKV projection partials.
// grid (H=16, NSL=32). Block (h, ds) handles d-slice [ds*32, ds*32+32).
// Thread owns dh = tid&63, b-group bg = tid>>6 (8 batches each), all 3 mats.
// Each W matrix element is read exactly once chip-wide; 512 CTAs for latency.
// ---------------------------------------------------------------------------
__global__ void __launch_bounds__(256) qkv_partial(
    const float* __restrict__ x,
    const float* __restrict__ Wq, const float* __restrict__ Wk,
    const float* __restrict__ Wv)
{
    const int h  = blockIdx.x;
    const int ds = blockIdx.y;
    const int tid = threadIdx.x;

    __shared__ float xs[BB][32];
    for (int i = tid; i < BB*32; i += 256) {
        int bb = i >> 5, dd = i & 31;
        xs[bb][dd] = x[bb*DD + ds*32 + dd];
    }
    __syncthreads();

    const int dh = tid & 63;
    const int bg = tid >> 6;          // 0..3
    const int wcol = h*DHH + dh;      // column in (H*DH)=1024

    float aq[8], ak[8], av[8];
#pragma unroll
    for (int j = 0; j < 8; j++) { aq[j]=0.f; ak[j]=0.f; av[j]=0.f; }

    const float* wqp = Wq + (size_t)(ds*32)*1024 + wcol;
    const float* wkp = Wk + (size_t)(ds*32)*1024 + wcol;
    const float* wvp = Wv + (size_t)(ds*32)*1024 + wcol;

#pragma unroll 8
    for (int d = 0; d < 32; d++) {
        float wq_ = wqp[(size_t)d*1024];
        float wk_ = wkp[(size_t)d*1024];
        float wv_ = wvp[(size_t)d*1024];
#pragma unroll
        for (int j = 0; j < 8; j++) {
            float xv = xs[bg*8 + j][d];   // broadcast within warp
            aq[j] += wq_ * xv;
            ak[j] += wk_ * xv;
            av[j] += wv_ * xv;
        }
    }
#pragma unroll
    for (int j = 0; j < 8; j++) {
        int b = bg*8 + j;
        int o = (b*HH + h)*DHH + dh;
        g_qp[ds][o] = aq[j];
        g_kp[ds][o] = ak[j];
        g_vp[ds][o] = av[j];
    }
}

// ---------------------------------------------------------------------------
// Kernel 2: attention (the HBM-bound part). grid = B*H = 512, 256 threads.
// Entry: fused reduce of q/kn/vn partials (+ biases) for this (b,h).
// Phase A: scores (warp-per-row, float2/lane, 4x t-unroll)
// Phase B: block softmax
// Phase C: weighted V sum (warp-strided t, float2/lane accumulators)
// ---------------------------------------------------------------------------
__global__ void __launch_bounds__(256) attn_kernel(
    const float* __restrict__ K, const float* __restrict__ V,
    const float* __restrict__ bq, const float* __restrict__ bk,
    const float* __restrict__ bv)
{
    const int bh   = blockIdx.x;
    const int b    = bh >> 4;
    const int h    = bh & 15;
    const int tid  = threadIdx.x;
    const int w    = tid >> 5;
    const int lane = tid & 31;
    const float scale = 0.125f;   // 1/sqrt(64)

    __shared__ float q_s[DHH];
    __shared__ float kn_s[DHH];
    __shared__ float vn_s[DHH];
    __shared__ float sc[NKV + 3];
    __shared__ float redm[8];
    __shared__ float reds[8];
    __shared__ float vred[8][DHH];

    // fused QKV partial reduction for this block's (b,h) slice
    if (tid < DHH) {
        const int i  = bh*DHH + tid;
        const int bi = h*DHH + tid;
        float sq = bq[bi], sk = bk[bi], sv = bv[bi];
#pragma unroll
        for (int s = 0; s < NSL; s++) {
            sq += g_qp[s][i];
            sk += g_kp[s][i];
            sv += g_vp[s][i];
        }
        q_s[tid] = sq; kn_s[tid] = sk; vn_s[tid] = sv;
    }
    __syncthreads();

    const float2 qv = make_float2(q_s[2*lane], q_s[2*lane + 1]);
    const float* kb = K + ((size_t)b*TT*HH + h)*DHH;   // row t at +t*1024

    // t = 4096 (new token) by warp 0
    if (w == 0) {
        float p = kn_s[2*lane]*qv.x + kn_s[2*lane+1]*qv.y;
#pragma unroll
        for (int o = 16; o; o >>= 1) p += __shfl_xor_sync(0xffffffffu, p, o);
        if (lane == 0) sc[TT] = p * scale;
    }

    // main score loop: each warp handles t = i + w, 4 unrolled per iter
    for (int i = 0; i < TT; i += 32) {
        int t = i + w;
        float2 k0 = ldf2(kb + (size_t)(t      )*1024 + 2*lane);
        float2 k1 = ldf2(kb + (size_t)(t +  8 )*1024 + 2*lane);
        float2 k2 = ldf2(kb + (size_t)(t + 16 )*1024 + 2*lane);
        float2 k3 = ldf2(kb + (size_t)(t + 24 )*1024 + 2*lane);
        float d0 = k0.x*qv.x + k0.y*qv.y;
        float d1 = k1.x*qv.x + k1.y*qv.y;
        float d2 = k2.x*qv.x + k2.y*qv.y;
        float d3 = k3.x*qv.x + k3.y*qv.y;
#pragma unroll
        for (int o = 16; o; o >>= 1) {
            d0 += __shfl_xor_sync(0xffffffffu, d0, o);
            d1 += __shfl_xor_sync(0xffffffffu, d1, o);
            d2 += __shfl_xor_sync(0xffffffffu, d2, o);
            d3 += __shfl_xor_sync(0xffffffffu, d3, o);
        }
        if (lane == 0) {
            sc[t]      = d0 * scale;
            sc[t +  8] = d1 * scale;
            sc[t + 16] = d2 * scale;
            sc[t + 24] = d3 * scale;
        }
    }
    __syncthreads();

    // softmax: block max
    float lm = -1e30f;
    for (int i = tid; i < NKV; i += 256) lm = fmaxf(lm, sc[i]);
#pragma unroll
    for (int o = 16; o; o >>= 1) lm = fmaxf(lm, __shfl_xor_sync(0xffffffffu, lm, o));
    if (lane == 0) redm[w] = lm;
    __syncthreads();
    float m = redm[0];
#pragma unroll
    for (int j = 1; j < 8; j++) m = fmaxf(m, redm[j]);

    // exp + block sum
    float ls = 0.f;
    for (int i = tid; i < NKV; i += 256) {
        float e = __expf(sc[i] - m);
        sc[i] = e;
        ls += e;
    }
#pragma unroll
    for (int o = 16; o; o >>= 1) ls += __shfl_xor_sync(0xffffffffu, ls, o);
    if (lane == 0) reds[w] = ls;
    __syncthreads();   // covers sc[] exp writes AND reds[]
    float denom = 0.f;
#pragma unroll
    for (int j = 0; j < 8; j++) denom += reds[j];
    const float inv = 1.0f / denom;

    // phase C: V accumulation, lane owns dh = {2*lane, 2*lane+1}
    const float* vb = V + ((size_t)b*TT*HH + h)*DHH;
    float ax = 0.f, ay = 0.f;
    for (int i = 0; i < TT; i += 32) {
        int t = i + w;
        float2 v0 = ldf2(vb + (size_t)(t      )*1024 + 2*lane);
        float2 v1 = ldf2(vb + (size_t)(t +  8 )*1024 + 2*lane);
        float2 v2 = ldf2(vb + (size_t)(t + 16 )*1024 + 2*lane);
        float2 v3 = ldf2(vb + (size_t)(t + 24 )*1024 + 2*lane);
        float p0 = sc[t], p1 = sc[t + 8], p2 = sc[t + 16], p3 = sc[t + 24];
        ax += p0*v0.x; ay += p0*v0.y;
        ax += p1*v1.x; ay += p1*v1.y;
        ax += p2*v2.x; ay += p2*v2.y;
        ax += p3*v3.x; ay += p3*v3.y;
    }
    if (w == 0) {
        float p = sc[TT];
        ax += p * vn_s[2*lane];
        ay += p * vn_s[2*lane + 1];
    }
    vred[w][2*lane]     = ax;
    vred[w][2*lane + 1] = ay;
    __syncthreads();
    if (tid < DHH) {
        float s2 = 0.f;
#pragma unroll
        for (int j = 0; j < 8; j++) s2 += vred[j][tid];
        g_ctx[bh*DHH + tid] = s2 * inv;
    }
}

// ---------------------------------------------------------------------------
// Kernel 3: output projection. Wo read exactly once chip-wide.
// grid (MC=16, KS=32). Thread owns m = mc*64 + (tid&63) and 8 batches.
// ---------------------------------------------------------------------------
__global__ void __launch_bounds__(256) out_partial(const float* __restrict__ Wo)
{
    const int mc = blockIdx.x;
    const int ks = blockIdx.y;
    const int tid = threadIdx.x;

    __shared__ float cs[BB][32];
    for (int i = tid; i < BB*32; i += 256) {
        int bb = i >> 5, kk = i & 31;
        cs[bb][kk] = g_ctx[bb*DD + ks*32 + kk];
    }
    __syncthreads();

    const int m  = mc*64 + (tid & 63);
    const int bg = tid >> 6;

    float acc[8];
#pragma unroll
    for (int j = 0; j < 8; j++) acc[j] = 0.f;

    const float* wp = Wo + (size_t)(ks*32)*1024 + m;
#pragma unroll 8
    for (int k = 0; k < 32; k++) {
        float w_ = wp[(size_t)k*1024];
#pragma unroll
        for (int j = 0; j < 8; j++)
            acc[j] += cs[bg*8 + j][k] * w_;
    }
#pragma unroll
    for (int j = 0; j < 8; j++)
        g_op[ks][(bg*8 + j)*DD + m] = acc[j];
}

__global__ void __launch_bounds__(256) out_reduce(
    const float* __restrict__ bo, float* __restrict__ out)
{
    int i = blockIdx.x * 256 + threadIdx.x;   // b*1024 + m
    float s = bo[i & 1023];
#pragma unroll
    for (int j = 0; j < NSL; j++) s += g_op[j][i];
    out[i] = s;
}

// ---------------------------------------------------------------------------
extern "C" void kernel_launch(void* const* d_in, const int* in_sizes, int n_in,
                              void* d_out, int out_size)
{
    const float* x     = (const float*)d_in[0];
    const float* ext_k = (const float*)d_in[1];
    const float* ext_v = (const float*)d_in[2];
    const float* Wq    = (const float*)d_in[3];
    const float* bq    = (const float*)d_in[4];
    const float* Wk    = (const float*)d_in[5];
    const float* bk    = (const float*)d_in[6];
    const float* Wv    = (const float*)d_in[7];
    const float* bv    = (const float*)d_in[8];
    const float* Wo    = (const float*)d_in[9];
    const float* bo    = (const float*)d_in[10];
    // d_in[11] = q_pos (fixed at 4096 by the dataset shapes)

    float* out = (float*)d_out;

    qkv_partial<<<dim3(HH, NSL), 256>>>(x, Wq, Wk, Wv);
    attn_kernel<<<NBH, 256>>>(ext_k, ext_v, bq, bk, bv);
    out_partial<<<dim3(16, NSL), 256>>>(Wo);
    out_reduce<<<NQ/256, 256>>>(bo, out);
}

// round 3
// speedup vs baseline: 1.2671x; 1.1169x over previous
#include <cuda_runtime.h>
#include <cuda_bf16.h>

// Problem constants (fixed by the dataset shapes)
#define BB   32
#define TT   4096
#define HH   16
#define DHH  64
#define DD   1024
#define NBH  (BB*HH)       // 512
#define NQ   (BB*HH*DHH)   // 32768
#define NSL  32            // split-K slices for projections
#define NSPLIT 2           // split-KV factor
#define TSP  (TT/NSPLIT)   // 2048 tokens per split

// Scratch (device globals; no allocation allowed)
__device__ float g_qp[NSL][NQ];
__device__ float g_kp[NSL][NQ];
__device__ float g_vp[NSL][NQ];
__device__ float g_cp[NSPLIT][NQ];     // unnormalized ctx partials
__device__ float g_ms[NBH][NSPLIT];    // local max
__device__ float g_ss[NBH][NSPLIT];    // local exp-sum
__device__ float g_ctx[NQ];
__device__ float g_op[NSL][NQ];

__device__ __forceinline__ float2 ldf2(const float* p) {
    return *reinterpret_cast<const float2*>(p);
}

// ---------------------------------------------------------------------------
// Kernel 1: QKV projection partials.
// grid (H=16, NSL=32). Block (h, ds) handles d-slice [ds*32, ds*32+32).
// ---------------------------------------------------------------------------
__global__ void __launch_bounds__(256) qkv_partial(
    const float* __restrict__ x,
    const float* __restrict__ Wq, const float* __restrict__ Wk,
    const float* __restrict__ Wv)
{
    const int h  = blockIdx.x;
    const int ds = blockIdx.y;
    const int tid = threadIdx.x;

    __shared__ float xs[BB][32];
    for (int i = tid; i < BB*32; i += 256) {
        int bb = i >> 5, dd = i & 31;
        xs[bb][dd] = x[bb*DD + ds*32 + dd];
    }
    __syncthreads();

    const int dh = tid & 63;
    const int bg = tid >> 6;          // 0..3
    const int wcol = h*DHH + dh;      // column in (H*DH)=1024

    float aq[8], ak[8], av[8];
#pragma unroll
    for (int j = 0; j < 8; j++) { aq[j]=0.f; ak[j]=0.f; av[j]=0.f; }

    const float* wqp = Wq + (size_t)(ds*32)*1024 + wcol;
    const float* wkp = Wk + (size_t)(ds*32)*1024 + wcol;
    const float* wvp = Wv + (size_t)(ds*32)*1024 + wcol;

#pragma unroll 8
    for (int d = 0; d < 32; d++) {
        float wq_ = wqp[(size_t)d*1024];
        float wk_ = wkp[(size_t)d*1024];
        float wv_ = wvp[(size_t)d*1024];
#pragma unroll
        for (int j = 0; j < 8; j++) {
            float xv = xs[bg*8 + j][d];
            aq[j] += wq_ * xv;
            ak[j] += wk_ * xv;
            av[j] += wv_ * xv;
        }
    }
#pragma unroll
    for (int j = 0; j < 8; j++) {
        int b = bg*8 + j;
        int o = (b*HH + h)*DHH + dh;
        g_qp[ds][o] = aq[j];
        g_kp[ds][o] = ak[j];
        g_vp[ds][o] = av[j];
    }
}

// ---------------------------------------------------------------------------
// Kernel 2: split-KV attention. grid = (B*H, NSPLIT), 256 threads.
// Each block handles TSP tokens (split 1 also owns the new token).
// Produces local max, local exp-sum, unnormalized ctx partial.
// ---------------------------------------------------------------------------
__global__ void __launch_bounds__(256) attn_split(
    const float* __restrict__ K, const float* __restrict__ V,
    const float* __restrict__ bq, const float* __restrict__ bk,
    const float* __restrict__ bv)
{
    const int bh   = blockIdx.x;
    const int sp   = blockIdx.y;
    const int b    = bh >> 4;
    const int h    = bh & 15;
    const int tid  = threadIdx.x;
    const int w    = tid >> 5;
    const int lane = tid & 31;
    const float scale = 0.125f;   // 1/sqrt(64)
    const int t0 = sp * TSP;
    const int nloc = TSP + (sp == NSPLIT-1 ? 1 : 0);

    __shared__ float q_s[DHH];
    __shared__ float kn_s[DHH];
    __shared__ float vn_s[DHH];
    __shared__ float sc[TSP + 1 + 3];
    __shared__ float redm[8];
    __shared__ float reds[8];
    __shared__ float vred[8][DHH];

    // fused QKV partial reduction for this block's (b,h) slice
    if (tid < DHH) {
        const int i  = bh*DHH + tid;
        const int bi = h*DHH + tid;
        float sq = bq[bi], sk = bk[bi], sv = bv[bi];
#pragma unroll
        for (int s = 0; s < NSL; s++) {
            sq += g_qp[s][i];
            sk += g_kp[s][i];
            sv += g_vp[s][i];
        }
        q_s[tid] = sq; kn_s[tid] = sk; vn_s[tid] = sv;
    }
    __syncthreads();

    const float2 qv = make_float2(q_s[2*lane], q_s[2*lane + 1]);
    const float* kb = K + ((size_t)b*TT*HH + h)*DHH + (size_t)t0*1024;

    // new token (only last split, warp 0)
    if (sp == NSPLIT-1 && w == 0) {
        float p = kn_s[2*lane]*qv.x + kn_s[2*lane+1]*qv.y;
#pragma unroll
        for (int o = 16; o; o >>= 1) p += __shfl_xor_sync(0xffffffffu, p, o);
        if (lane == 0) sc[TSP] = p * scale;
    }

    // score loop: warp handles rows i+w, i+w+8, ..., i+w+56 (8x unroll)
    for (int i = 0; i < TSP; i += 64) {
        int t = i + w;
        float d[8];
#pragma unroll
        for (int r = 0; r < 8; r++) {
            float2 kk = ldf2(kb + (size_t)(t + 8*r)*1024 + 2*lane);
            d[r] = kk.x*qv.x + kk.y*qv.y;
        }
#pragma unroll
        for (int o = 16; o; o >>= 1) {
#pragma unroll
            for (int r = 0; r < 8; r++)
                d[r] += __shfl_xor_sync(0xffffffffu, d[r], o);
        }
        if (lane == 0) {
#pragma unroll
            for (int r = 0; r < 8; r++)
                sc[t + 8*r] = d[r] * scale;
        }
    }
    __syncthreads();

    // local softmax: block max
    float lm = -1e30f;
    for (int i = tid; i < nloc; i += 256) lm = fmaxf(lm, sc[i]);
#pragma unroll
    for (int o = 16; o; o >>= 1) lm = fmaxf(lm, __shfl_xor_sync(0xffffffffu, lm, o));
    if (lane == 0) redm[w] = lm;
    __syncthreads();
    float m = redm[0];
#pragma unroll
    for (int j = 1; j < 8; j++) m = fmaxf(m, redm[j]);

    // exp + local sum
    float ls = 0.f;
    for (int i = tid; i < nloc; i += 256) {
        float e = __expf(sc[i] - m);
        sc[i] = e;
        ls += e;
    }
#pragma unroll
    for (int o = 16; o; o >>= 1) ls += __shfl_xor_sync(0xffffffffu, ls, o);
    if (lane == 0) reds[w] = ls;
    __syncthreads();
    float lsum = 0.f;
#pragma unroll
    for (int j = 0; j < 8; j++) lsum += reds[j];

    // phase C: unnormalized V accumulation, lane owns dh = {2*lane, 2*lane+1}
    const float* vb = V + ((size_t)b*TT*HH + h)*DHH + (size_t)t0*1024;
    float ax = 0.f, ay = 0.f;
    for (int i = 0; i < TSP; i += 64) {
        int t = i + w;
#pragma unroll
        for (int r = 0; r < 8; r++) {
            float2 vv = ldf2(vb + (size_t)(t + 8*r)*1024 + 2*lane);
            float p = sc[t + 8*r];
            ax += p*vv.x; ay += p*vv.y;
        }
    }
    if (sp == NSPLIT-1 && w == 0) {
        float p = sc[TSP];
        ax += p * vn_s[2*lane];
        ay += p * vn_s[2*lane + 1];
    }
    vred[w][2*lane]     = ax;
    vred[w][2*lane + 1] = ay;
    __syncthreads();
    if (tid < DHH) {
        float s2 = 0.f;
#pragma unroll
        for (int j = 0; j < 8; j++) s2 += vred[j][tid];
        g_cp[sp][bh*DHH + tid] = s2;
        if (tid == 0) { g_ms[bh][sp] = m; g_ss[bh][sp] = lsum; }
    }
}

// ---------------------------------------------------------------------------
// Kernel 2b: combine split partials into g_ctx.
// ---------------------------------------------------------------------------
__global__ void __launch_bounds__(256) attn_combine()
{
    int i  = blockIdx.x * 256 + threadIdx.x;  // bh*64 + dh
    int bh = i >> 6;
    float m0 = g_ms[bh][0], m1 = g_ms[bh][1];
    float s0 = g_ss[bh][0], s1 = g_ss[bh][1];
    float M  = fmaxf(m0, m1);
    float w0 = __expf(m0 - M), w1 = __expf(m1 - M);
    float denom = w0*s0 + w1*s1;
    g_ctx[i] = (w0*g_cp[0][i] + w1*g_cp[1][i]) / denom;
}

// ---------------------------------------------------------------------------
// Kernel 3: output projection. grid (MC=16, KS=32).
// ---------------------------------------------------------------------------
__global__ void __launch_bounds__(256) out_partial(const float* __restrict__ Wo)
{
    const int mc = blockIdx.x;
    const int ks = blockIdx.y;
    const int tid = threadIdx.x;

    __shared__ float cs[BB][32];
    for (int i = tid; i < BB*32; i += 256) {
        int bb = i >> 5, kk = i & 31;
        cs[bb][kk] = g_ctx[bb*DD + ks*32 + kk];
    }
    __syncthreads();

    const int m  = mc*64 + (tid & 63);
    const int bg = tid >> 6;

    float acc[8];
#pragma unroll
    for (int j = 0; j < 8; j++) acc[j] = 0.f;

    const float* wp = Wo + (size_t)(ks*32)*1024 + m;
#pragma unroll 8
    for (int k = 0; k < 32; k++) {
        float w_ = wp[(size_t)k*1024];
#pragma unroll
        for (int j = 0; j < 8; j++)
            acc[j] += cs[bg*8 + j][k] * w_;
    }
#pragma unroll
    for (int j = 0; j < 8; j++)
        g_op[ks][(bg*8 + j)*DD + m] = acc[j];
}

__global__ void __launch_bounds__(256) out_reduce(
    const float* __restrict__ bo, float* __restrict__ out)
{
    int i = blockIdx.x * 256 + threadIdx.x;   // b*1024 + m
    float s = bo[i & 1023];
#pragma unroll
    for (int j = 0; j < NSL; j++) s += g_op[j][i];
    out[i] = s;
}

// ---------------------------------------------------------------------------
extern "C" void kernel_launch(void* const* d_in, const int* in_sizes, int n_in,
                              void* d_out, int out_size)
{
    const float* x     = (const float*)d_in[0];
    const float* ext_k = (const float*)d_in[1];
    const float* ext_v = (const float*)d_in[2];
    const float* Wq    = (const float*)d_in[3];
    const float* bq    = (const float*)d_in[4];
    const float* Wk    = (const float*)d_in[5];
    const float* bk    = (const float*)d_in[6];
    const float* Wv    = (const float*)d_in[7];
    const float* bv    = (const float*)d_in[8];
    const float* Wo    = (const float*)d_in[9];
    const float* bo    = (const float*)d_in[10];
    // d_in[11] = q_pos (fixed at 4096 by the dataset shapes)

    float* out = (float*)d_out;

    qkv_partial<<<dim3(HH, NSL), 256>>>(x, Wq, Wk, Wv);
    attn_split<<<dim3(NBH, NSPLIT), 256>>>(ext_k, ext_v, bq, bk, bv);
    attn_combine<<<NQ/256, 256>>>();
    out_partial<<<dim3(16, NSL), 256>>>(Wo);
    out_reduce<<<NQ/256, 256>>>(bo, out);
}

// round 4
// speedup vs baseline: 1.2938x; 1.0210x over previous
#include <cuda_runtime.h>
#include <cuda_bf16.h>

// Problem constants (fixed by the dataset shapes)
#define BB   32
#define TT   4096
#define HH   16
#define DHH  64
#define DD   1024
#define NBH  (BB*HH)       // 512
#define NQ   (BB*HH*DHH)   // 32768
#define NSL  32            // split-K slices for projections
#define NSPLIT 4           // split-KV factor
#define TSP  (TT/NSPLIT)   // 1024 tokens per split

// Scratch (device globals; no allocation allowed)
__device__ float g_qp[NSL][NQ];
__device__ float g_kp[NSL][NQ];
__device__ float g_vp[NSL][NQ];
__device__ float g_cp[NSPLIT][NQ];     // unnormalized ctx partials
__device__ float g_ms[NBH][NSPLIT];    // local max
__device__ float g_ss[NBH][NSPLIT];    // local exp-sum
__device__ float g_op[NSL][NQ];

__device__ __forceinline__ float2 ldf2(const float* p) {
    return *reinterpret_cast<const float2*>(p);
}
__device__ __forceinline__ float4 ldf4(const float* p) {
    return *reinterpret_cast<const float4*>(p);
}

// ---------------------------------------------------------------------------
// Kernel 1: QKV projection partials, smem-staged weights.
// grid (H=16, NSL=32). Block (h, ds) handles d-slice [ds*32, ds*32+32).
// Weight tiles (32x64 per matrix) loaded coalesced to smem once (zero
// redundancy, 6 LDG.128/thread front-batched), FMA loop runs from smem.
// ---------------------------------------------------------------------------
__global__ void __launch_bounds__(256) qkv_partial(
    const float* __restrict__ x,
    const float* __restrict__ Wq, const float* __restrict__ Wk,
    const float* __restrict__ Wv)
{
    const int h  = blockIdx.x;
    const int ds = blockIdx.y;
    const int tid = threadIdx.x;

    __shared__ float xs[BB][32];
    __shared__ float wsq[32][64];
    __shared__ float wsk[32][64];
    __shared__ float wsv[32][64];

    // stage weight tiles: 512 float4 per matrix, 2 per thread per matrix
#pragma unroll
    for (int i = tid; i < 512; i += 256) {
        int row = i >> 4;
        int c4  = (i & 15) * 4;
        size_t off = (size_t)(ds*32 + row)*1024 + h*DHH + c4;
        *(float4*)&wsq[row][c4] = ldf4(Wq + off);
        *(float4*)&wsk[row][c4] = ldf4(Wk + off);
        *(float4*)&wsv[row][c4] = ldf4(Wv + off);
    }
    for (int i = tid; i < BB*32; i += 256) {
        int bb = i >> 5, dd = i & 31;
        xs[bb][dd] = x[bb*DD + ds*32 + dd];
    }
    __syncthreads();

    const int dh = tid & 63;
    const int bg = tid >> 6;          // 0..3, 8 batches each

    float aq[8], ak[8], av[8];
#pragma unroll
    for (int j = 0; j < 8; j++) { aq[j]=0.f; ak[j]=0.f; av[j]=0.f; }

#pragma unroll 8
    for (int d = 0; d < 32; d++) {
        float wq_ = wsq[d][dh];
        float wk_ = wsk[d][dh];
        float wv_ = wsv[d][dh];
#pragma unroll
        for (int j = 0; j < 8; j++) {
            float xv = xs[bg*8 + j][d];
            aq[j] += wq_ * xv;
            ak[j] += wk_ * xv;
            av[j] += wv_ * xv;
        }
    }
#pragma unroll
    for (int j = 0; j < 8; j++) {
        int b = bg*8 + j;
        int o = (b*HH + h)*DHH + dh;
        g_qp[ds][o] = aq[j];
        g_kp[ds][o] = ak[j];
        g_vp[ds][o] = av[j];
    }
}

// ---------------------------------------------------------------------------
// Kernel 2: split-KV attention. grid = (B*H, NSPLIT), 256 threads.
// Each block handles TSP=1024 tokens (last split also owns the new token).
// Produces local max, local exp-sum, unnormalized ctx partial.
// ---------------------------------------------------------------------------
__global__ void __launch_bounds__(256) attn_split(
    const float* __restrict__ K, const float* __restrict__ V,
    const float* __restrict__ bq, const float* __restrict__ bk,
    const float* __restrict__ bv)
{
    const int bh   = blockIdx.x;
    const int sp   = blockIdx.y;
    const int b    = bh >> 4;
    const int h    = bh & 15;
    const int tid  = threadIdx.x;
    const int w    = tid >> 5;
    const int lane = tid & 31;
    const int t0 = sp * TSP;
    const int nloc = TSP + (sp == NSPLIT-1 ? 1 : 0);

    __shared__ float q_s[DHH];     // pre-scaled by 1/sqrt(DH)
    __shared__ float kn_s[DHH];
    __shared__ float vn_s[DHH];
    __shared__ float sc[TSP + 1 + 3];
    __shared__ float redm[8];
    __shared__ float reds[8];
    __shared__ float vred[8][DHH];

    // fused QKV partial reduction for this block's (b,h) slice
    if (tid < DHH) {
        const int i  = bh*DHH + tid;
        const int bi = h*DHH + tid;
        float sq = bq[bi], sk = bk[bi], sv = bv[bi];
#pragma unroll
        for (int s = 0; s < NSL; s++) {
            sq += g_qp[s][i];
            sk += g_kp[s][i];
            sv += g_vp[s][i];
        }
        q_s[tid] = sq * 0.125f;   // fold scale into q
        kn_s[tid] = sk; vn_s[tid] = sv;
    }
    __syncthreads();

    const float2 qv = make_float2(q_s[2*lane], q_s[2*lane + 1]);
    const float* kb = K + ((size_t)b*TT*HH + h)*DHH + (size_t)t0*1024;

    // new token (only last split, warp 0)
    if (sp == NSPLIT-1 && w == 0) {
        float p = kn_s[2*lane]*qv.x + kn_s[2*lane+1]*qv.y;
#pragma unroll
        for (int o = 16; o; o >>= 1) p += __shfl_xor_sync(0xffffffffu, p, o);
        if (lane == 0) sc[TSP] = p;
    }

    // score loop: warp handles rows i+w, i+w+8, ..., i+w+56 (8x unroll)
    for (int i = 0; i < TSP; i += 64) {
        int t = i + w;
        float d[8];
#pragma unroll
        for (int r = 0; r < 8; r++) {
            float2 kk = ldf2(kb + (size_t)(t + 8*r)*1024 + 2*lane);
            d[r] = kk.x*qv.x + kk.y*qv.y;
        }
#pragma unroll
        for (int o = 16; o; o >>= 1) {
#pragma unroll
            for (int r = 0; r < 8; r++)
                d[r] += __shfl_xor_sync(0xffffffffu, d[r], o);
        }
        if (lane == 0) {
#pragma unroll
            for (int r = 0; r < 8; r++)
                sc[t + 8*r] = d[r];
        }
    }
    __syncthreads();

    // local softmax: block max
    float lm = -1e30f;
    for (int i = tid; i < nloc; i += 256) lm = fmaxf(lm, sc[i]);
#pragma unroll
    for (int o = 16; o; o >>= 1) lm = fmaxf(lm, __shfl_xor_sync(0xffffffffu, lm, o));
    if (lane == 0) redm[w] = lm;
    __syncthreads();
    float m = redm[0];
#pragma unroll
    for (int j = 1; j < 8; j++) m = fmaxf(m, redm[j]);

    // exp + local sum
    float ls = 0.f;
    for (int i = tid; i < nloc; i += 256) {
        float e = __expf(sc[i] - m);
        sc[i] = e;
        ls += e;
    }
#pragma unroll
    for (int o = 16; o; o >>= 1) ls += __shfl_xor_sync(0xffffffffu, ls, o);
    if (lane == 0) reds[w] = ls;
    __syncthreads();
    float lsum = 0.f;
#pragma unroll
    for (int j = 0; j < 8; j++) lsum += reds[j];

    // phase C: unnormalized V accumulation, lane owns dh = {2*lane, 2*lane+1}
    const float* vb = V + ((size_t)b*TT*HH + h)*DHH + (size_t)t0*1024;
    float ax = 0.f, ay = 0.f;
    for (int i = 0; i < TSP; i += 64) {
        int t = i + w;
#pragma unroll
        for (int r = 0; r < 8; r++) {
            float2 vv = ldf2(vb + (size_t)(t + 8*r)*1024 + 2*lane);
            float p = sc[t + 8*r];
            ax += p*vv.x; ay += p*vv.y;
        }
    }
    if (sp == NSPLIT-1 && w == 0) {
        float p = sc[TSP];
        ax += p * vn_s[2*lane];
        ay += p * vn_s[2*lane + 1];
    }
    vred[w][2*lane]     = ax;
    vred[w][2*lane + 1] = ay;
    __syncthreads();
    if (tid < DHH) {
        float s2 = 0.f;
#pragma unroll
        for (int j = 0; j < 8; j++) s2 += vred[j][tid];
        g_cp[sp][bh*DHH + tid] = s2;
        if (tid == 0) { g_ms[bh][sp] = m; g_ss[bh][sp] = lsum; }
    }
}

// ---------------------------------------------------------------------------
// Kernel 3: output projection with fused split-combine, smem-staged Wo.
// grid (MC=16, KS=32). Block handles 64 m-cols x 32 k. Per block, the
// k-slice [ks*32, ks*32+32) maps to a single head h = ks/2.
// ---------------------------------------------------------------------------
__global__ void __launch_bounds__(256) out_partial(const float* __restrict__ Wo)
{
    const int mc = blockIdx.x;
    const int ks = blockIdx.y;
    const int tid = threadIdx.x;
    const int h  = ks >> 1;
    const int dhb = (ks & 1) * 32;

    __shared__ float cs[BB][32];
    __shared__ float ws[32][64];
    __shared__ float wgt[NSPLIT][BB];

    // split-combine weights for the 32 (b, h) rows this block touches
    if (tid < BB) {
        const int bh = tid*HH + h;
        float m0 = g_ms[bh][0], m1 = g_ms[bh][1];
        float m2 = g_ms[bh][2], m3 = g_ms[bh][3];
        float M = fmaxf(fmaxf(m0, m1), fmaxf(m2, m3));
        float e0 = __expf(m0 - M), e1 = __expf(m1 - M);
        float e2 = __expf(m2 - M), e3 = __expf(m3 - M);
        float denom = e0*g_ss[bh][0] + e1*g_ss[bh][1]
                    + e2*g_ss[bh][2] + e3*g_ss[bh][3];
        float inv = 1.0f / denom;
        wgt[0][tid] = e0*inv; wgt[1][tid] = e1*inv;
        wgt[2][tid] = e2*inv; wgt[3][tid] = e3*inv;
    }

    // stage Wo tile: 32 k-rows x 64 m-cols, coalesced float4
#pragma unroll
    for (int i = tid; i < 512; i += 256) {
        int row = i >> 4;
        int c4  = (i & 15) * 4;
        *(float4*)&ws[row][c4] = ldf4(Wo + (size_t)(ks*32 + row)*1024 + mc*64 + c4);
    }
    __syncthreads();

    // build cs = combined normalized ctx for (b, k-slice)
    for (int i = tid; i < BB*32; i += 256) {
        int bb = i >> 5, kk = i & 31;
        int o = (bb*HH + h)*DHH + dhb + kk;
        cs[bb][kk] = wgt[0][bb]*g_cp[0][o] + wgt[1][bb]*g_cp[1][o]
                   + wgt[2][bb]*g_cp[2][o] + wgt[3][bb]*g_cp[3][o];
    }
    __syncthreads();

    const int m  = tid & 63;
    const int bg = tid >> 6;

    float acc[8];
#pragma unroll
    for (int j = 0; j < 8; j++) acc[j] = 0.f;

#pragma unroll 8
    for (int k = 0; k < 32; k++) {
        float w_ = ws[k][m];
#pragma unroll
        for (int j = 0; j < 8; j++)
            acc[j] += cs[bg*8 + j][k] * w_;
    }
#pragma unroll
    for (int j = 0; j < 8; j++)
        g_op[ks][(bg*8 + j)*DD + mc*64 + m] = acc[j];
}

__global__ void __launch_bounds__(64) out_reduce(
    const float* __restrict__ bo, float* __restrict__ out)
{
    int i = (blockIdx.x * 64 + threadIdx.x) * 4;   // b*1024 + m, float4
    float4 s = ldf4(bo + (i & 1023));
#pragma unroll
    for (int j = 0; j < NSL; j++) {
        float4 v = ldf4(&g_op[j][i]);
        s.x += v.x; s.y += v.y; s.z += v.z; s.w += v.w;
    }
    *(float4*)(out + i) = s;
}

// ---------------------------------------------------------------------------
extern "C" void kernel_launch(void* const* d_in, const int* in_sizes, int n_in,
                              void* d_out, int out_size)
{
    const float* x     = (const float*)d_in[0];
    const float* ext_k = (const float*)d_in[1];
    const float* ext_v = (const float*)d_in[2];
    const float* Wq    = (const float*)d_in[3];
    const float* bq    = (const float*)d_in[4];
    const float* Wk    = (const float*)d_in[5];
    const float* bk    = (const float*)d_in[6];
    const float* Wv    = (const float*)d_in[7];
    const float* bv    = (const float*)d_in[8];
    const float* Wo    = (const float*)d_in[9];
    const float* bo    = (const float*)d_in[10];
    // d_in[11] = q_pos (fixed at 4096 by the dataset shapes)

    float* out = (float*)d_out;

    qkv_partial<<<dim3(HH, NSL), 256>>>(x, Wq, Wk, Wv);
    attn_split<<<dim3(NBH, NSPLIT), 256>>>(ext_k, ext_v, bq, bk, bv);
    out_partial<<<dim3(16, NSL), 256>>>(Wo);
    out_reduce<<<NQ/(64*4), 64>>>(bo, out);
}

// round 5
// speedup vs baseline: 1.3310x; 1.0288x over previous
#include <cuda_runtime.h>
#include <cuda_bf16.h>

// Problem constants (fixed by the dataset shapes)
#define BB   32
#define TT   4096
#define HH   16
#define DHH  64
#define DD   1024
#define NBH  (BB*HH)       // 512
#define NQ   (BB*HH*DHH)   // 32768
#define NSL  32            // split-K slices for projections
#define NSPLIT 4           // split-KV factor
#define TSP  (TT/NSPLIT)   // 1024 tokens per split

// Scratch (device globals; no allocation allowed)
__device__ float g_qp[NSL][NQ];
__device__ float g_kp[NSL][NQ];
__device__ float g_vp[NSL][NQ];
__device__ float g_q [NQ];             // reduced, pre-scaled
__device__ float g_kn[NQ];
__device__ float g_vn[NQ];
__device__ float g_cp[NSPLIT][NQ];     // unnormalized ctx partials
__device__ float g_ms[NBH][NSPLIT];    // local max
__device__ float g_ss[NBH][NSPLIT];    // local exp-sum
__device__ float g_op[NSL][NQ];

__device__ __forceinline__ float2 ldf2(const float* p) {
    return *reinterpret_cast<const float2*>(p);
}
__device__ __forceinline__ float4 ldf4(const float* p) {
    return *reinterpret_cast<const float4*>(p);
}

// ---------------------------------------------------------------------------
// Kernel 1: QKV projection partials, smem-staged weights.
// grid (H=16, NSL=32). Block (h, ds) handles d-slice [ds*32, ds*32+32).
// ---------------------------------------------------------------------------
__global__ void __launch_bounds__(256) qkv_partial(
    const float* __restrict__ x,
    const float* __restrict__ Wq, const float* __restrict__ Wk,
    const float* __restrict__ Wv)
{
    const int h  = blockIdx.x;
    const int ds = blockIdx.y;
    const int tid = threadIdx.x;

    __shared__ float xs[BB][32];
    __shared__ float wsq[32][64];
    __shared__ float wsk[32][64];
    __shared__ float wsv[32][64];

    // stage weight tiles: 512 float4 per matrix, 2 per thread per matrix
#pragma unroll
    for (int i = tid; i < 512; i += 256) {
        int row = i >> 4;
        int c4  = (i & 15) * 4;
        size_t off = (size_t)(ds*32 + row)*1024 + h*DHH + c4;
        *(float4*)&wsq[row][c4] = ldf4(Wq + off);
        *(float4*)&wsk[row][c4] = ldf4(Wk + off);
        *(float4*)&wsv[row][c4] = ldf4(Wv + off);
    }
    for (int i = tid; i < BB*32; i += 256) {
        int bb = i >> 5, dd = i & 31;
        xs[bb][dd] = x[bb*DD + ds*32 + dd];
    }
    __syncthreads();

    const int dh = tid & 63;
    const int bg = tid >> 6;          // 0..3, 8 batches each

    float aq[8], ak[8], av[8];
#pragma unroll
    for (int j = 0; j < 8; j++) { aq[j]=0.f; ak[j]=0.f; av[j]=0.f; }

#pragma unroll 8
    for (int d = 0; d < 32; d++) {
        float wq_ = wsq[d][dh];
        float wk_ = wsk[d][dh];
        float wv_ = wsv[d][dh];
#pragma unroll
        for (int j = 0; j < 8; j++) {
            float xv = xs[bg*8 + j][d];
            aq[j] += wq_ * xv;
            ak[j] += wk_ * xv;
            av[j] += wv_ * xv;
        }
    }
#pragma unroll
    for (int j = 0; j < 8; j++) {
        int b = bg*8 + j;
        int o = (b*HH + h)*DHH + dh;
        g_qp[ds][o] = aq[j];
        g_kp[ds][o] = ak[j];
        g_vp[ds][o] = av[j];
    }
}

// ---------------------------------------------------------------------------
// Kernel 1b: reduce QKV partials. grid 128 x 256.
// Block owns 64 float4 positions; thread group (tid>>6) sums 8 of 32 slices.
// ---------------------------------------------------------------------------
__global__ void __launch_bounds__(256) qkv_reduce(
    const float* __restrict__ bq, const float* __restrict__ bk,
    const float* __restrict__ bv)
{
    const int tid = threadIdx.x;
    const int pos = tid & 63;             // local f4 position
    const int grp = tid >> 6;             // 0..3
    const int p   = blockIdx.x * 64 + pos;  // global f4 index, < 8192
    const int i   = p * 4;

    __shared__ float4 pq[4][64];
    __shared__ float4 pk[4][64];
    __shared__ float4 pv[4][64];

    float4 sq = make_float4(0,0,0,0), sk = sq, sv = sq;
#pragma unroll
    for (int j = 0; j < 8; j++) {
        int s = grp*8 + j;
        float4 a = ldf4(&g_qp[s][i]);
        float4 b2 = ldf4(&g_kp[s][i]);
        float4 c = ldf4(&g_vp[s][i]);
        sq.x += a.x; sq.y += a.y; sq.z += a.z; sq.w += a.w;
        sk.x += b2.x; sk.y += b2.y; sk.z += b2.z; sk.w += b2.w;
        sv.x += c.x; sv.y += c.y; sv.z += c.z; sv.w += c.w;
    }
    pq[grp][pos] = sq; pk[grp][pos] = sk; pv[grp][pos] = sv;
    __syncthreads();

    if (grp == 0) {
        int bi = i & 1023;                // (h*64+dh)
        float4 xq = ldf4(bq + bi), xk = ldf4(bk + bi), xv = ldf4(bv + bi);
#pragma unroll
        for (int g = 0; g < 4; g++) {
            float4 a = pq[g][pos], b2 = pk[g][pos], c = pv[g][pos];
            xq.x += a.x; xq.y += a.y; xq.z += a.z; xq.w += a.w;
            xk.x += b2.x; xk.y += b2.y; xk.z += b2.z; xk.w += b2.w;
            xv.x += c.x; xv.y += c.y; xv.z += c.z; xv.w += c.w;
        }
        xq.x *= 0.125f; xq.y *= 0.125f; xq.z *= 0.125f; xq.w *= 0.125f;
        *(float4*)&g_q[i]  = xq;
        *(float4*)&g_kn[i] = xk;
        *(float4*)&g_vn[i] = xv;
    }
}

// ---------------------------------------------------------------------------
// Kernel 2: split-KV attention. grid = (B*H, NSPLIT), 256 threads.
// ---------------------------------------------------------------------------
__global__ void __launch_bounds__(256) attn_split(
    const float* __restrict__ K, const float* __restrict__ V)
{
    const int bh   = blockIdx.x;
    const int sp   = blockIdx.y;
    const int b    = bh >> 4;
    const int h    = bh & 15;
    const int tid  = threadIdx.x;
    const int w    = tid >> 5;
    const int lane = tid & 31;
    const int t0 = sp * TSP;
    const int nloc = TSP + (sp == NSPLIT-1 ? 1 : 0);

    __shared__ float q_s[DHH];     // pre-scaled by 1/sqrt(DH)
    __shared__ float kn_s[DHH];
    __shared__ float vn_s[DHH];
    __shared__ float sc[TSP + 1 + 3];
    __shared__ float redm[8];
    __shared__ float reds[8];
    __shared__ float vred[8][DHH];

    if (tid < DHH) {
        const int i = bh*DHH + tid;
        q_s[tid]  = g_q[i];
        kn_s[tid] = g_kn[i];
        vn_s[tid] = g_vn[i];
    }
    __syncthreads();

    const float2 qv = make_float2(q_s[2*lane], q_s[2*lane + 1]);
    const float* kb = K + ((size_t)b*TT*HH + h)*DHH + (size_t)t0*1024;

    // new token (only last split, warp 0)
    if (sp == NSPLIT-1 && w == 0) {
        float p = kn_s[2*lane]*qv.x + kn_s[2*lane+1]*qv.y;
#pragma unroll
        for (int o = 16; o; o >>= 1) p += __shfl_xor_sync(0xffffffffu, p, o);
        if (lane == 0) sc[TSP] = p;
    }

    // score loop: warp handles rows i+w, i+w+8, ..., i+w+56 (8x unroll)
    for (int i = 0; i < TSP; i += 64) {
        int t = i + w;
        float d[8];
#pragma unroll
        for (int r = 0; r < 8; r++) {
            float2 kk = ldf2(kb + (size_t)(t + 8*r)*1024 + 2*lane);
            d[r] = kk.x*qv.x + kk.y*qv.y;
        }
#pragma unroll
        for (int o = 16; o; o >>= 1) {
#pragma unroll
            for (int r = 0; r < 8; r++)
                d[r] += __shfl_xor_sync(0xffffffffu, d[r], o);
        }
        if (lane == 0) {
#pragma unroll
            for (int r = 0; r < 8; r++)
                sc[t + 8*r] = d[r];
        }
    }
    __syncthreads();

    // local softmax: block max
    float lm = -1e30f;
    for (int i = tid; i < nloc; i += 256) lm = fmaxf(lm, sc[i]);
#pragma unroll
    for (int o = 16; o; o >>= 1) lm = fmaxf(lm, __shfl_xor_sync(0xffffffffu, lm, o));
    if (lane == 0) redm[w] = lm;
    __syncthreads();
    float m = redm[0];
#pragma unroll
    for (int j = 1; j < 8; j++) m = fmaxf(m, redm[j]);

    // exp + local sum
    float ls = 0.f;
    for (int i = tid; i < nloc; i += 256) {
        float e = __expf(sc[i] - m);
        sc[i] = e;
        ls += e;
    }
#pragma unroll
    for (int o = 16; o; o >>= 1) ls += __shfl_xor_sync(0xffffffffu, ls, o);
    if (lane == 0) reds[w] = ls;
    __syncthreads();
    float lsum = 0.f;
#pragma unroll
    for (int j = 0; j < 8; j++) lsum += reds[j];

    // phase C: unnormalized V accumulation, lane owns dh = {2*lane, 2*lane+1}
    const float* vb = V + ((size_t)b*TT*HH + h)*DHH + (size_t)t0*1024;
    float ax = 0.f, ay = 0.f;
    for (int i = 0; i < TSP; i += 64) {
        int t = i + w;
#pragma unroll
        for (int r = 0; r < 8; r++) {
            float2 vv = ldf2(vb + (size_t)(t + 8*r)*1024 + 2*lane);
            float p = sc[t + 8*r];
            ax += p*vv.x; ay += p*vv.y;
        }
    }
    if (sp == NSPLIT-1 && w == 0) {
        float p = sc[TSP];
        ax += p * vn_s[2*lane];
        ay += p * vn_s[2*lane + 1];
    }
    vred[w][2*lane]     = ax;
    vred[w][2*lane + 1] = ay;
    __syncthreads();
    if (tid < DHH) {
        float s2 = 0.f;
#pragma unroll
        for (int j = 0; j < 8; j++) s2 += vred[j][tid];
        g_cp[sp][bh*DHH + tid] = s2;
        if (tid == 0) { g_ms[bh][sp] = m; g_ss[bh][sp] = lsum; }
    }
}

// ---------------------------------------------------------------------------
// Kernel 3: output projection with fused split-combine, smem-staged Wo.
// grid (MC=16, KS=32). Per block, k-slice [ks*32, ..) maps to head h = ks/2.
// ---------------------------------------------------------------------------
__global__ void __launch_bounds__(256) out_partial(const float* __restrict__ Wo)
{
    const int mc = blockIdx.x;
    const int ks = blockIdx.y;
    const int tid = threadIdx.x;
    const int h  = ks >> 1;
    const int dhb = (ks & 1) * 32;

    __shared__ float cs[BB][32];
    __shared__ float ws[32][64];
    __shared__ float wgt[NSPLIT][BB];

    // split-combine weights for the 32 (b, h) rows this block touches
    if (tid < BB) {
        const int bh = tid*HH + h;
        float m0 = g_ms[bh][0], m1 = g_ms[bh][1];
        float m2 = g_ms[bh][2], m3 = g_ms[bh][3];
        float M = fmaxf(fmaxf(m0, m1), fmaxf(m2, m3));
        float e0 = __expf(m0 - M), e1 = __expf(m1 - M);
        float e2 = __expf(m2 - M), e3 = __expf(m3 - M);
        float denom = e0*g_ss[bh][0] + e1*g_ss[bh][1]
                    + e2*g_ss[bh][2] + e3*g_ss[bh][3];
        float inv = 1.0f / denom;
        wgt[0][tid] = e0*inv; wgt[1][tid] = e1*inv;
        wgt[2][tid] = e2*inv; wgt[3][tid] = e3*inv;
    }

    // stage Wo tile: 32 k-rows x 64 m-cols, coalesced float4
#pragma unroll
    for (int i = tid; i < 512; i += 256) {
        int row = i >> 4;
        int c4  = (i & 15) * 4;
        *(float4*)&ws[row][c4] = ldf4(Wo + (size_t)(ks*32 + row)*1024 + mc*64 + c4);
    }
    __syncthreads();

    // build cs = combined normalized ctx for (b, k-slice)
    for (int i = tid; i < BB*32; i += 256) {
        int bb = i >> 5, kk = i & 31;
        int o = (bb*HH + h)*DHH + dhb + kk;
        cs[bb][kk] = wgt[0][bb]*g_cp[0][o] + wgt[1][bb]*g_cp[1][o]
                   + wgt[2][bb]*g_cp[2][o] + wgt[3][bb]*g_cp[3][o];
    }
    __syncthreads();

    const int m  = tid & 63;
    const int bg = tid >> 6;

    float acc[8];
#pragma unroll
    for (int j = 0; j < 8; j++) acc[j] = 0.f;

#pragma unroll 8
    for (int k = 0; k < 32; k++) {
        float w_ = ws[k][m];
#pragma unroll
        for (int j = 0; j < 8; j++)
            acc[j] += cs[bg*8 + j][k] * w_;
    }
#pragma unroll
    for (int j = 0; j < 8; j++)
        g_op[ks][(bg*8 + j)*DD + mc*64 + m] = acc[j];
}

// ---------------------------------------------------------------------------
// Kernel 3b: reduce output partials. grid 128 x 256, slice-parallel.
// ---------------------------------------------------------------------------
__global__ void __launch_bounds__(256) out_reduce(
    const float* __restrict__ bo, float* __restrict__ out)
{
    const int tid = threadIdx.x;
    const int pos = tid & 63;
    const int grp = tid >> 6;
    const int p   = blockIdx.x * 64 + pos;
    const int i   = p * 4;

    __shared__ float4 ps[4][64];

    float4 s = make_float4(0,0,0,0);
#pragma unroll
    for (int j = 0; j < 8; j++) {
        float4 v = ldf4(&g_op[grp*8 + j][i]);
        s.x += v.x; s.y += v.y; s.z += v.z; s.w += v.w;
    }
    ps[grp][pos] = s;
    __syncthreads();

    if (grp == 0) {
        float4 r = ldf4(bo + (i & 1023));
#pragma unroll
        for (int g = 0; g < 4; g++) {
            float4 v = ps[g][pos];
            r.x += v.x; r.y += v.y; r.z += v.z; r.w += v.w;
        }
        *(float4*)(out + i) = r;
    }
}

// ---------------------------------------------------------------------------
extern "C" void kernel_launch(void* const* d_in, const int* in_sizes, int n_in,
                              void* d_out, int out_size)
{
    const float* x     = (const float*)d_in[0];
    const float* ext_k = (const float*)d_in[1];
    const float* ext_v = (const float*)d_in[2];
    const float* Wq    = (const float*)d_in[3];
    const float* bq    = (const float*)d_in[4];
    const float* Wk    = (const float*)d_in[5];
    const float* bk    = (const float*)d_in[6];
    const float* Wv    = (const float*)d_in[7];
    const float* bv    = (const float*)d_in[8];
    const float* Wo    = (const float*)d_in[9];
    const float* bo    = (const float*)d_in[10];
    // d_in[11] = q_pos (fixed at 4096 by the dataset shapes)

    float* out = (float*)d_out;

    qkv_partial<<<dim3(HH, NSL), 256>>>(x, Wq, Wk, Wv);
    qkv_reduce<<<128, 256>>>(bq, bk, bv);
    attn_split<<<dim3(NBH, NSPLIT), 256>>>(ext_k, ext_v);
    out_partial<<<dim3(16, NSL), 256>>>(Wo);
    out_reduce<<<128, 256>>>(bo, out);
}

// round 6
// speedup vs baseline: 1.3507x; 1.0148x over previous
#include <cuda_runtime.h>
#include <cuda_bf16.h>

// Problem constants (fixed by the dataset shapes)
#define BB   32
#define TT   4096
#define HH   16
#define DHH  64
#define DD   1024
#define NBH  (BB*HH)       // 512
#define NQ   (BB*HH*DHH)   // 32768
#define NSL  32            // split-K slices for projections
#define NSPLIT 4           // split-KV factor
#define TSP  (TT/NSPLIT)   // 1024 tokens per split

// Scratch (device globals; no allocation allowed)
__device__ float g_qp[NSL][NQ];
__device__ float g_kp[NSL][NQ];
__device__ float g_vp[NSL][NQ];
__device__ float g_q [NQ];             // reduced, pre-scaled
__device__ float g_kn[NQ];
__device__ float g_vn[NQ];
__device__ float g_cp[NSPLIT][NQ];     // unnormalized ctx partials
__device__ float g_ms[NBH][NSPLIT];    // local max
__device__ float g_ss[NBH][NSPLIT];    // local exp-sum
__device__ float g_op[NSL][NQ];

__device__ __forceinline__ float4 ldf4(const float* p) {
    return *reinterpret_cast<const float4*>(p);
}

// ---------------------------------------------------------------------------
// Kernel 1: QKV projection partials, smem-staged weights.
// grid (H=16, NSL=32). Block (h, ds) handles d-slice [ds*32, ds*32+32).
// ---------------------------------------------------------------------------
__global__ void __launch_bounds__(256) qkv_partial(
    const float* __restrict__ x,
    const float* __restrict__ Wq, const float* __restrict__ Wk,
    const float* __restrict__ Wv)
{
    const int h  = blockIdx.x;
    const int ds = blockIdx.y;
    const int tid = threadIdx.x;

    __shared__ float xs[BB][32];
    __shared__ float wsq[32][64];
    __shared__ float wsk[32][64];
    __shared__ float wsv[32][64];

#pragma unroll
    for (int i = tid; i < 512; i += 256) {
        int row = i >> 4;
        int c4  = (i & 15) * 4;
        size_t off = (size_t)(ds*32 + row)*1024 + h*DHH + c4;
        *(float4*)&wsq[row][c4] = ldf4(Wq + off);
        *(float4*)&wsk[row][c4] = ldf4(Wk + off);
        *(float4*)&wsv[row][c4] = ldf4(Wv + off);
    }
    for (int i = tid; i < BB*32; i += 256) {
        int bb = i >> 5, dd = i & 31;
        xs[bb][dd] = x[bb*DD + ds*32 + dd];
    }
    __syncthreads();

    const int dh = tid & 63;
    const int bg = tid >> 6;          // 0..3, 8 batches each

    float aq[8], ak[8], av[8];
#pragma unroll
    for (int j = 0; j < 8; j++) { aq[j]=0.f; ak[j]=0.f; av[j]=0.f; }

#pragma unroll 8
    for (int d = 0; d < 32; d++) {
        float wq_ = wsq[d][dh];
        float wk_ = wsk[d][dh];
        float wv_ = wsv[d][dh];
#pragma unroll
        for (int j = 0; j < 8; j++) {
            float xv = xs[bg*8 + j][d];
            aq[j] += wq_ * xv;
            ak[j] += wk_ * xv;
            av[j] += wv_ * xv;
        }
    }
#pragma unroll
    for (int j = 0; j < 8; j++) {
        int b = bg*8 + j;
        int o = (b*HH + h)*DHH + dh;
        g_qp[ds][o] = aq[j];
        g_kp[ds][o] = ak[j];
        g_vp[ds][o] = av[j];
    }
}

// ---------------------------------------------------------------------------
// Kernel 1b: reduce QKV partials. grid 128 x 256, slice-parallel.
// ---------------------------------------------------------------------------
__global__ void __launch_bounds__(256) qkv_reduce(
    const float* __restrict__ bq, const float* __restrict__ bk,
    const float* __restrict__ bv)
{
    const int tid = threadIdx.x;
    const int pos = tid & 63;
    const int grp = tid >> 6;
    const int i   = (blockIdx.x * 64 + pos) * 4;

    __shared__ float4 pq[4][64];
    __shared__ float4 pk[4][64];
    __shared__ float4 pv[4][64];

    float4 sq = make_float4(0,0,0,0), sk = sq, sv = sq;
#pragma unroll
    for (int j = 0; j < 8; j++) {
        int s = grp*8 + j;
        float4 a = ldf4(&g_qp[s][i]);
        float4 b2 = ldf4(&g_kp[s][i]);
        float4 c = ldf4(&g_vp[s][i]);
        sq.x += a.x; sq.y += a.y; sq.z += a.z; sq.w += a.w;
        sk.x += b2.x; sk.y += b2.y; sk.z += b2.z; sk.w += b2.w;
        sv.x += c.x; sv.y += c.y; sv.z += c.z; sv.w += c.w;
    }
    pq[grp][pos] = sq; pk[grp][pos] = sk; pv[grp][pos] = sv;
    __syncthreads();

    if (grp == 0) {
        int bi = i & 1023;
        float4 xq = ldf4(bq + bi), xk = ldf4(bk + bi), xv = ldf4(bv + bi);
#pragma unroll
        for (int g = 0; g < 4; g++) {
            float4 a = pq[g][pos], b2 = pk[g][pos], c = pv[g][pos];
            xq.x += a.x; xq.y += a.y; xq.z += a.z; xq.w += a.w;
            xk.x += b2.x; xk.y += b2.y; xk.z += b2.z; xk.w += b2.w;
            xv.x += c.x; xv.y += c.y; xv.z += c.z; xv.w += c.w;
        }
        xq.x *= 0.125f; xq.y *= 0.125f; xq.z *= 0.125f; xq.w *= 0.125f;
        *(float4*)&g_q[i]  = xq;
        *(float4*)&g_kn[i] = xk;
        *(float4*)&g_vn[i] = xv;
    }
}

// ---------------------------------------------------------------------------
// Kernel 2: split-KV attention. grid = (B*H, NSPLIT), 256 threads.
// Phase A: float4 loads, 16 lanes/row (2 rows per warp-load), 16 rows/warp/iter.
// Phase C: float4 loads/accumulators, per-half-warp partials.
// ---------------------------------------------------------------------------
__global__ void __launch_bounds__(256) attn_split(
    const float* __restrict__ K, const float* __restrict__ V)
{
    const int bh   = blockIdx.x;
    const int sp   = blockIdx.y;
    const int b    = bh >> 4;
    const int h    = bh & 15;
    const int tid  = threadIdx.x;
    const int w    = tid >> 5;
    const int lane = tid & 31;
    const int half = lane >> 4;       // 0 or 1
    const int hl   = lane & 15;       // lane within half
    const int t0 = sp * TSP;
    const int nloc = TSP + (sp == NSPLIT-1 ? 1 : 0);

    __shared__ float q_s[DHH];     // pre-scaled by 1/sqrt(DH)
    __shared__ float kn_s[DHH];
    __shared__ float vn_s[DHH];
    __shared__ float sc[TSP + 1 + 3];
    __shared__ float redm[8];
    __shared__ float reds[8];
    __shared__ float vred[8][2][DHH];

    if (tid < DHH) {
        const int i = bh*DHH + tid;
        q_s[tid]  = g_q[i];
        kn_s[tid] = g_kn[i];
        vn_s[tid] = g_vn[i];
    }
    __syncthreads();

    const float4 q4 = ldf4(&q_s[hl*4]);
    const float* kb = K + ((size_t)b*TT*HH + h)*DHH + (size_t)t0*1024;

    // new token (last split, warp 0, lanes 0-15)
    if (sp == NSPLIT-1 && w == 0 && lane < 16) {
        float4 kn4 = ldf4(&kn_s[lane*4]);
        float p = kn4.x*q4.x + kn4.y*q4.y + kn4.z*q4.z + kn4.w*q4.w;
#pragma unroll
        for (int o = 8; o; o >>= 1) p += __shfl_xor_sync(0xffffu, p, o);
        if (lane == 0) sc[TSP] = p;
    }

    // scores: warp handles 16 rows/iter; lane-half owns row parity
    for (int i = 0; i < TSP; i += 128) {
        int rbase = i + w*16 + half;
        float d[8];
#pragma unroll
        for (int s = 0; s < 8; s++) {
            float4 kk = ldf4(kb + (size_t)(rbase + 2*s)*1024 + hl*4);
            d[s] = kk.x*q4.x + kk.y*q4.y + kk.z*q4.z + kk.w*q4.w;
        }
#pragma unroll
        for (int o = 8; o; o >>= 1) {
#pragma unroll
            for (int s = 0; s < 8; s++)
                d[s] += __shfl_xor_sync(0xffffffffu, d[s], o);
        }
        if (hl == 0) {
#pragma unroll
            for (int s = 0; s < 8; s++)
                sc[rbase + 2*s] = d[s];
        }
    }
    __syncthreads();

    // local softmax: block max
    float lm = -1e30f;
    for (int i = tid; i < nloc; i += 256) lm = fmaxf(lm, sc[i]);
#pragma unroll
    for (int o = 16; o; o >>= 1) lm = fmaxf(lm, __shfl_xor_sync(0xffffffffu, lm, o));
    if (lane == 0) redm[w] = lm;
    __syncthreads();
    float m = redm[0];
#pragma unroll
    for (int j = 1; j < 8; j++) m = fmaxf(m, redm[j]);

    // exp + local sum
    float ls = 0.f;
    for (int i = tid; i < nloc; i += 256) {
        float e = __expf(sc[i] - m);
        sc[i] = e;
        ls += e;
    }
#pragma unroll
    for (int o = 16; o; o >>= 1) ls += __shfl_xor_sync(0xffffffffu, ls, o);
    if (lane == 0) reds[w] = ls;
    __syncthreads();
    float lsum = 0.f;
#pragma unroll
    for (int j = 0; j < 8; j++) lsum += reds[j];

    // phase C: unnormalized V accumulation; lane owns dh = hl*4..hl*4+3
    const float* vb = V + ((size_t)b*TT*HH + h)*DHH + (size_t)t0*1024;
    float4 acc = make_float4(0,0,0,0);
    for (int i = 0; i < TSP; i += 128) {
        int rbase = i + w*16 + half;
#pragma unroll
        for (int s = 0; s < 8; s++) {
            float4 vv = ldf4(vb + (size_t)(rbase + 2*s)*1024 + hl*4);
            float p = sc[rbase + 2*s];
            acc.x += p*vv.x; acc.y += p*vv.y; acc.z += p*vv.z; acc.w += p*vv.w;
        }
    }
    if (sp == NSPLIT-1 && w == 0 && lane < 16) {
        float p = sc[TSP];
        float4 vn4 = ldf4(&vn_s[lane*4]);
        acc.x += p*vn4.x; acc.y += p*vn4.y; acc.z += p*vn4.z; acc.w += p*vn4.w;
    }
    *(float4*)&vred[w][half][hl*4] = acc;
    __syncthreads();
    if (tid < DHH) {
        float s2 = 0.f;
#pragma unroll
        for (int j = 0; j < 8; j++)
            s2 += vred[j][0][tid] + vred[j][1][tid];
        g_cp[sp][bh*DHH + tid] = s2;
        if (tid == 0) { g_ms[bh][sp] = m; g_ss[bh][sp] = lsum; }
    }
}

// ---------------------------------------------------------------------------
// Kernel 3: output projection with fused split-combine, smem-staged Wo.
// All global loads front-batched to registers before the first sync; the
// wgt exp chain runs in their shadow. grid (MC=16, KS=32).
// ---------------------------------------------------------------------------
__global__ void __launch_bounds__(256) out_partial(const float* __restrict__ Wo)
{
    const int mc = blockIdx.x;
    const int ks = blockIdx.y;
    const int tid = threadIdx.x;
    const int h  = ks >> 1;
    const int dhb = (ks & 1) * 32;

    __shared__ float cs[BB][32];
    __shared__ float ws[32][64];
    __shared__ float wgt[NSPLIT][BB];

    // front-batch: ctx partials (16 scalar loads/thread, to registers)
    float pv[4][NSPLIT];
#pragma unroll
    for (int it = 0; it < 4; it++) {
        int i = tid + it*256;
        int bb = i >> 5, kk = i & 31;
        int o = (bb*HH + h)*DHH + dhb + kk;
#pragma unroll
        for (int s = 0; s < NSPLIT; s++) pv[it][s] = g_cp[s][o];
    }

    // front-batch: Wo tile (coalesced float4)
#pragma unroll
    for (int i = tid; i < 512; i += 256) {
        int row = i >> 4;
        int c4  = (i & 15) * 4;
        *(float4*)&ws[row][c4] = ldf4(Wo + (size_t)(ks*32 + row)*1024 + mc*64 + c4);
    }

    // split-combine weights (tid<32); exp chain hides under the loads above
    if (tid < BB) {
        const int bh = tid*HH + h;
        float m0 = g_ms[bh][0], m1 = g_ms[bh][1];
        float m2 = g_ms[bh][2], m3 = g_ms[bh][3];
        float M = fmaxf(fmaxf(m0, m1), fmaxf(m2, m3));
        float e0 = __expf(m0 - M), e1 = __expf(m1 - M);
        float e2 = __expf(m2 - M), e3 = __expf(m3 - M);
        float denom = e0*g_ss[bh][0] + e1*g_ss[bh][1]
                    + e2*g_ss[bh][2] + e3*g_ss[bh][3];
        float inv = 1.0f / denom;
        wgt[0][tid] = e0*inv; wgt[1][tid] = e1*inv;
        wgt[2][tid] = e2*inv; wgt[3][tid] = e3*inv;
    }
    __syncthreads();

    // combine from registers
#pragma unroll
    for (int it = 0; it < 4; it++) {
        int i = tid + it*256;
        int bb = i >> 5, kk = i & 31;
        cs[bb][kk] = wgt[0][bb]*pv[it][0] + wgt[1][bb]*pv[it][1]
                   + wgt[2][bb]*pv[it][2] + wgt[3][bb]*pv[it][3];
    }
    __syncthreads();

    const int m  = tid & 63;
    const int bg = tid >> 6;

    float acc[8];
#pragma unroll
    for (int j = 0; j < 8; j++) acc[j] = 0.f;

#pragma unroll 8
    for (int k = 0; k < 32; k++) {
        float w_ = ws[k][m];
#pragma unroll
        for (int j = 0; j < 8; j++)
            acc[j] += cs[bg*8 + j][k] * w_;
    }
#pragma unroll
    for (int j = 0; j < 8; j++)
        g_op[ks][(bg*8 + j)*DD + mc*64 + m] = acc[j];
}

// ---------------------------------------------------------------------------
// Kernel 3b: reduce output partials. grid 128 x 256, slice-parallel.
// ---------------------------------------------------------------------------
__global__ void __launch_bounds__(256) out_reduce(
    const float* __restrict__ bo, float* __restrict__ out)
{
    const int tid = threadIdx.x;
    const int pos = tid & 63;
    const int grp = tid >> 6;
    const int i   = (blockIdx.x * 64 + pos) * 4;

    __shared__ float4 ps[4][64];

    float4 s = make_float4(0,0,0,0);
#pragma unroll
    for (int j = 0; j < 8; j++) {
        float4 v = ldf4(&g_op[grp*8 + j][i]);
        s.x += v.x; s.y += v.y; s.z += v.z; s.w += v.w;
    }
    ps[grp][pos] = s;
    __syncthreads();

    if (grp == 0) {
        float4 r = ldf4(bo + (i & 1023));
#pragma unroll
        for (int g = 0; g < 4; g++) {
            float4 v = ps[g][pos];
            r.x += v.x; r.y += v.y; r.z += v.z; r.w += v.w;
        }
        *(float4*)(out + i) = r;
    }
}

// ---------------------------------------------------------------------------
extern "C" void kernel_launch(void* const* d_in, const int* in_sizes, int n_in,
                              void* d_out, int out_size)
{
    const float* x     = (const float*)d_in[0];
    const float* ext_k = (const float*)d_in[1];
    const float* ext_v = (const float*)d_in[2];
    const float* Wq    = (const float*)d_in[3];
    const float* bq    = (const float*)d_in[4];
    const float* Wk    = (const float*)d_in[5];
    const float* bk    = (const float*)d_in[6];
    const float* Wv    = (const float*)d_in[7];
    const float* bv    = (const float*)d_in[8];
    const float* Wo    = (const float*)d_in[9];
    const float* bo    = (const float*)d_in[10];
    // d_in[11] = q_pos (fixed at 4096 by the dataset shapes)

    float* out = (float*)d_out;

    qkv_partial<<<dim3(HH, NSL), 256>>>(x, Wq, Wk, Wv);
    qkv_reduce<<<128, 256>>>(bq, bk, bv);
    attn_split<<<dim3(NBH, NSPLIT), 256>>>(ext_k, ext_v);
    out_partial<<<dim3(16, NSL), 256>>>(Wo);
    out_reduce<<<128, 256>>>(bo, out);
}

// round 7
// speedup vs baseline: 1.4095x; 1.0435x over previous
#include <cuda_runtime.h>
#include <cuda_bf16.h>

// Problem constants (fixed by the dataset shapes)
#define BB   32
#define TT   4096
#define HH   16
#define DHH  64
#define DD   1024
#define NBH  (BB*HH)       // 512
#define NQ   (BB*HH*DHH)   // 32768
#define NSL  32            // split-K slices for projections
#define NSPLIT 4           // split-KV factor
#define TSP  (TT/NSPLIT)   // 1024 tokens per split

// Scratch (device globals; no allocation allowed)
__device__ float g_qp[NSL][NQ];
__device__ float g_kp[NSL][NQ];
__device__ float g_vp[NSL][NQ];
__device__ float g_q [NQ];             // reduced, pre-scaled
__device__ float g_kn[NQ];
__device__ float g_vn[NQ];
__device__ float g_cp[NSPLIT][NQ];     // unnormalized ctx partials
__device__ float g_ms[NBH][NSPLIT];    // local max
__device__ float g_ss[NBH][NSPLIT];    // local exp-sum
__device__ float g_op[NSL][NQ];

__device__ __forceinline__ float4 ldf4(const float* p) {
    return *reinterpret_cast<const float4*>(p);
}

// ---------------------------------------------------------------------------
// Kernel 1: QKV projection partials, smem-staged weights.
// grid (H=16, NSL=32). Block (h, ds) handles d-slice [ds*32, ds*32+32).
// ---------------------------------------------------------------------------
__global__ void __launch_bounds__(256) qkv_partial(
    const float* __restrict__ x,
    const float* __restrict__ Wq, const float* __restrict__ Wk,
    const float* __restrict__ Wv)
{
    const int h  = blockIdx.x;
    const int ds = blockIdx.y;
    const int tid = threadIdx.x;

    __shared__ float xs[BB][32];
    __shared__ float wsq[32][64];
    __shared__ float wsk[32][64];
    __shared__ float wsv[32][64];

#pragma unroll
    for (int i = tid; i < 512; i += 256) {
        int row = i >> 4;
        int c4  = (i & 15) * 4;
        size_t off = (size_t)(ds*32 + row)*1024 + h*DHH + c4;
        *(float4*)&wsq[row][c4] = ldf4(Wq + off);
        *(float4*)&wsk[row][c4] = ldf4(Wk + off);
        *(float4*)&wsv[row][c4] = ldf4(Wv + off);
    }
    for (int i = tid; i < BB*32; i += 256) {
        int bb = i >> 5, dd = i & 31;
        xs[bb][dd] = x[bb*DD + ds*32 + dd];
    }
    __syncthreads();

    const int dh = tid & 63;
    const int bg = tid >> 6;          // 0..3, 8 batches each

    float aq[8], ak[8], av[8];
#pragma unroll
    for (int j = 0; j < 8; j++) { aq[j]=0.f; ak[j]=0.f; av[j]=0.f; }

#pragma unroll 8
    for (int d = 0; d < 32; d++) {
        float wq_ = wsq[d][dh];
        float wk_ = wsk[d][dh];
        float wv_ = wsv[d][dh];
#pragma unroll
        for (int j = 0; j < 8; j++) {
            float xv = xs[bg*8 + j][d];
            aq[j] += wq_ * xv;
            ak[j] += wk_ * xv;
            av[j] += wv_ * xv;
        }
    }
#pragma unroll
    for (int j = 0; j < 8; j++) {
        int b = bg*8 + j;
        int o = (b*HH + h)*DHH + dh;
        g_qp[ds][o] = aq[j];
        g_kp[ds][o] = ak[j];
        g_vp[ds][o] = av[j];
    }
}

// ---------------------------------------------------------------------------
// Kernel 1b: reduce QKV partials. grid 128 x 256, slice-parallel.
// ---------------------------------------------------------------------------
__global__ void __launch_bounds__(256) qkv_reduce(
    const float* __restrict__ bq, const float* __restrict__ bk,
    const float* __restrict__ bv)
{
    const int tid = threadIdx.x;
    const int pos = tid & 63;
    const int grp = tid >> 6;
    const int i   = (blockIdx.x * 64 + pos) * 4;

    __shared__ float4 pq[4][64];
    __shared__ float4 pk[4][64];
    __shared__ float4 pv[4][64];

    float4 sq = make_float4(0,0,0,0), sk = sq, sv = sq;
#pragma unroll
    for (int j = 0; j < 8; j++) {
        int s = grp*8 + j;
        float4 a = ldf4(&g_qp[s][i]);
        float4 b2 = ldf4(&g_kp[s][i]);
        float4 c = ldf4(&g_vp[s][i]);
        sq.x += a.x; sq.y += a.y; sq.z += a.z; sq.w += a.w;
        sk.x += b2.x; sk.y += b2.y; sk.z += b2.z; sk.w += b2.w;
        sv.x += c.x; sv.y += c.y; sv.z += c.z; sv.w += c.w;
    }
    pq[grp][pos] = sq; pk[grp][pos] = sk; pv[grp][pos] = sv;
    __syncthreads();

    if (grp == 0) {
        int bi = i & 1023;
        float4 xq = ldf4(bq + bi), xk = ldf4(bk + bi), xv = ldf4(bv + bi);
#pragma unroll
        for (int g = 0; g < 4; g++) {
            float4 a = pq[g][pos], b2 = pk[g][pos], c = pv[g][pos];
            xq.x += a.x; xq.y += a.y; xq.z += a.z; xq.w += a.w;
            xk.x += b2.x; xk.y += b2.y; xk.z += b2.z; xk.w += b2.w;
            xv.x += c.x; xv.y += c.y; xv.z += c.z; xv.w += c.w;
        }
        xq.x *= 0.125f; xq.y *= 0.125f; xq.z *= 0.125f; xq.w *= 0.125f;
        *(float4*)&g_q[i]  = xq;
        *(float4*)&g_kn[i] = xk;
        *(float4*)&g_vn[i] = xv;
    }
}

// ---------------------------------------------------------------------------
// Kernel 2: single-pass online-softmax split-KV attention.
// grid = (B*H, NSPLIT), 256 threads. Per 128-row iter each warp front-batches
// 8 K-rows + 8 V-rows (16 LDG.128 in flight), computes scores, then one
// running-max rescale + 8 exp-weighted V accumulations. No mid-kernel
// block barriers, no score array.
// ---------------------------------------------------------------------------
__global__ void __launch_bounds__(256) attn_split(
    const float* __restrict__ K, const float* __restrict__ V)
{
    const int bh   = blockIdx.x;
    const int sp   = blockIdx.y;
    const int b    = bh >> 4;
    const int h    = bh & 15;
    const int tid  = threadIdx.x;
    const int w    = tid >> 5;
    const int lane = tid & 31;
    const int half = lane >> 4;       // 0 or 1
    const int hl   = lane & 15;       // lane within half
    const int t0 = sp * TSP;

    __shared__ float q_s[DHH];        // pre-scaled by 1/sqrt(DH)
    __shared__ float kn_s[DHH];
    __shared__ float vn_s[DHH];
    __shared__ float mred[8][2];
    __shared__ float lred[8][2];
    __shared__ float vred[8][2][DHH];

    if (tid < DHH) {
        const int i = bh*DHH + tid;
        q_s[tid]  = g_q[i];
        kn_s[tid] = g_kn[i];
        vn_s[tid] = g_vn[i];
    }
    __syncthreads();

    const float4 q4 = ldf4(&q_s[hl*4]);
    const float* kb = K + ((size_t)b*TT*HH + h)*DHH + (size_t)t0*1024;
    const float* vb = V + ((size_t)b*TT*HH + h)*DHH + (size_t)t0*1024;

    float m_run = -1e30f;
    float l_run = 0.f;
    float4 acc = make_float4(0,0,0,0);

    for (int i = 0; i < TSP; i += 128) {
        const int rbase = i + w*16 + half;

        // front-batch all 16 loads before any consume
        float4 kk[8], vv[8];
#pragma unroll
        for (int s = 0; s < 8; s++)
            kk[s] = ldf4(kb + (size_t)(rbase + 2*s)*1024 + hl*4);
#pragma unroll
        for (int s = 0; s < 8; s++)
            vv[s] = ldf4(vb + (size_t)(rbase + 2*s)*1024 + hl*4);

        // scores: partial dot per lane, reduce over 16-lane half
        float d[8];
#pragma unroll
        for (int s = 0; s < 8; s++)
            d[s] = kk[s].x*q4.x + kk[s].y*q4.y + kk[s].z*q4.z + kk[s].w*q4.w;
#pragma unroll
        for (int o = 8; o; o >>= 1) {
#pragma unroll
            for (int s = 0; s < 8; s++)
                d[s] += __shfl_xor_sync(0xffffffffu, d[s], o);
        }

        // online softmax update (one rescale per 8 rows)
        float bm = d[0];
#pragma unroll
        for (int s = 1; s < 8; s++) bm = fmaxf(bm, d[s]);
        float nm = fmaxf(m_run, bm);
        float cs = __expf(m_run - nm);
        l_run *= cs;
        acc.x *= cs; acc.y *= cs; acc.z *= cs; acc.w *= cs;
#pragma unroll
        for (int s = 0; s < 8; s++) {
            float p = __expf(d[s] - nm);
            l_run += p;
            acc.x += p*vv[s].x; acc.y += p*vv[s].y;
            acc.z += p*vv[s].z; acc.w += p*vv[s].w;
        }
        m_run = nm;
    }

    // new token (last split, warp 0, half 0)
    if (sp == NSPLIT-1 && w == 0 && lane < 16) {
        float4 kn4 = ldf4(&kn_s[lane*4]);
        float p = kn4.x*q4.x + kn4.y*q4.y + kn4.z*q4.z + kn4.w*q4.w;
#pragma unroll
        for (int o = 8; o; o >>= 1) p += __shfl_xor_sync(0xffffu, p, o);
        float nm = fmaxf(m_run, p);
        float cs = __expf(m_run - nm);
        l_run *= cs;
        acc.x *= cs; acc.y *= cs; acc.z *= cs; acc.w *= cs;
        float pe = __expf(p - nm);
        l_run += pe;
        float4 vn4 = ldf4(&vn_s[lane*4]);
        acc.x += pe*vn4.x; acc.y += pe*vn4.y;
        acc.z += pe*vn4.z; acc.w += pe*vn4.w;
        m_run = nm;
    }

    // stash per-(warp, half) partials
    if (hl == 0) { mred[w][half] = m_run; lred[w][half] = l_run; }
    *(float4*)&vred[w][half][hl*4] = acc;
    __syncthreads();

    // cross-warp combine (64 threads, one per dh)
    if (tid < DHH) {
        float M = -1e30f;
#pragma unroll
        for (int j = 0; j < 8; j++) {
            M = fmaxf(M, mred[j][0]);
            M = fmaxf(M, mred[j][1]);
        }
        float denom = 0.f, s2 = 0.f;
#pragma unroll
        for (int j = 0; j < 8; j++) {
#pragma unroll
            for (int k2 = 0; k2 < 2; k2++) {
                float e = __expf(mred[j][k2] - M);
                denom += e * lred[j][k2];
                s2    += e * vred[j][k2][tid];
            }
        }
        g_cp[sp][bh*DHH + tid] = s2;
        if (tid == 0) { g_ms[bh][sp] = M; g_ss[bh][sp] = denom; }
    }
}

// ---------------------------------------------------------------------------
// Kernel 3: output projection with fused split-combine, smem-staged Wo.
// All global loads front-batched before the first sync. grid (MC=16, KS=32).
// ---------------------------------------------------------------------------
__global__ void __launch_bounds__(256) out_partial(const float* __restrict__ Wo)
{
    const int mc = blockIdx.x;
    const int ks = blockIdx.y;
    const int tid = threadIdx.x;
    const int h  = ks >> 1;
    const int dhb = (ks & 1) * 32;

    __shared__ float cs[BB][32];
    __shared__ float ws[32][64];
    __shared__ float wgt[NSPLIT][BB];

    // front-batch: ctx partials (16 scalar loads/thread, to registers)
    float pv[4][NSPLIT];
#pragma unroll
    for (int it = 0; it < 4; it++) {
        int i = tid + it*256;
        int bb = i >> 5, kk = i & 31;
        int o = (bb*HH + h)*DHH + dhb + kk;
#pragma unroll
        for (int s = 0; s < NSPLIT; s++) pv[it][s] = g_cp[s][o];
    }

    // front-batch: Wo tile (coalesced float4)
#pragma unroll
    for (int i = tid; i < 512; i += 256) {
        int row = i >> 4;
        int c4  = (i & 15) * 4;
        *(float4*)&ws[row][c4] = ldf4(Wo + (size_t)(ks*32 + row)*1024 + mc*64 + c4);
    }

    // split-combine weights (tid<32); exp chain hides under the loads above
    if (tid < BB) {
        const int bh = tid*HH + h;
        float m0 = g_ms[bh][0], m1 = g_ms[bh][1];
        float m2 = g_ms[bh][2], m3 = g_ms[bh][3];
        float M = fmaxf(fmaxf(m0, m1), fmaxf(m2, m3));
        float e0 = __expf(m0 - M), e1 = __expf(m1 - M);
        float e2 = __expf(m2 - M), e3 = __expf(m3 - M);
        float denom = e0*g_ss[bh][0] + e1*g_ss[bh][1]
                    + e2*g_ss[bh][2] + e3*g_ss[bh][3];
        float inv = 1.0f / denom;
        wgt[0][tid] = e0*inv; wgt[1][tid] = e1*inv;
        wgt[2][tid] = e2*inv; wgt[3][tid] = e3*inv;
    }
    __syncthreads();

    // combine from registers
#pragma unroll
    for (int it = 0; it < 4; it++) {
        int i = tid + it*256;
        int bb = i >> 5, kk = i & 31;
        cs[bb][kk] = wgt[0][bb]*pv[it][0] + wgt[1][bb]*pv[it][1]
                   + wgt[2][bb]*pv[it][2] + wgt[3][bb]*pv[it][3];
    }
    __syncthreads();

    const int m  = tid & 63;
    const int bg = tid >> 6;

    float acc[8];
#pragma unroll
    for (int j = 0; j < 8; j++) acc[j] = 0.f;

#pragma unroll 8
    for (int k = 0; k < 32; k++) {
        float w_ = ws[k][m];
#pragma unroll
        for (int j = 0; j < 8; j++)
            acc[j] += cs[bg*8 + j][k] * w_;
    }
#pragma unroll
    for (int j = 0; j < 8; j++)
        g_op[ks][(bg*8 + j)*DD + mc*64 + m] = acc[j];
}

// ---------------------------------------------------------------------------
// Kernel 3b: reduce output partials. grid 128 x 256, slice-parallel.
// ---------------------------------------------------------------------------
__global__ void __launch_bounds__(256) out_reduce(
    const float* __restrict__ bo, float* __restrict__ out)
{
    const int tid = threadIdx.x;
    const int pos = tid & 63;
    const int grp = tid >> 6;
    const int i   = (blockIdx.x * 64 + pos) * 4;

    __shared__ float4 ps[4][64];

    float4 s = make_float4(0,0,0,0);
#pragma unroll
    for (int j = 0; j < 8; j++) {
        float4 v = ldf4(&g_op[grp*8 + j][i]);
        s.x += v.x; s.y += v.y; s.z += v.z; s.w += v.w;
    }
    ps[grp][pos] = s;
    __syncthreads();

    if (grp == 0) {
        float4 r = ldf4(bo + (i & 1023));
#pragma unroll
        for (int g = 0; g < 4; g++) {
            float4 v = ps[g][pos];
            r.x += v.x; r.y += v.y; r.z += v.z; r.w += v.w;
        }
        *(float4*)(out + i) = r;
    }
}

// ---------------------------------------------------------------------------
extern "C" void kernel_launch(void* const* d_in, const int* in_sizes, int n_in,
                              void* d_out, int out_size)
{
    const float* x     = (const float*)d_in[0];
    const float* ext_k = (const float*)d_in[1];
    const float* ext_v = (const float*)d_in[2];
    const float* Wq    = (const float*)d_in[3];
    const float* bq    = (const float*)d_in[4];
    const float* Wk    = (const float*)d_in[5];
    const float* bk    = (const float*)d_in[6];
    const float* Wv    = (const float*)d_in[7];
    const float* bv    = (const float*)d_in[8];
    const float* Wo    = (const float*)d_in[9];
    const float* bo    = (const float*)d_in[10];
    // d_in[11] = q_pos (fixed at 4096 by the dataset shapes)

    float* out = (float*)d_out;

    qkv_partial<<<dim3(HH, NSL), 256>>>(x, Wq, Wk, Wv);
    qkv_reduce<<<128, 256>>>(bq, bk, bv);
    attn_split<<<dim3(NBH, NSPLIT), 256>>>(ext_k, ext_v);
    out_partial<<<dim3(16, NSL), 256>>>(Wo);
    out_reduce<<<128, 256>>>(bo, out);
}

// round 8
// speedup vs baseline: 1.4423x; 1.0233x over previous
#include <cuda_runtime.h>
#include <cuda_bf16.h>

// Problem constants (fixed by the dataset shapes)
#define BB   32
#define TT   4096
#define HH   16
#define DHH  64
#define DD   1024
#define NBH  (BB*HH)       // 512
#define NQ   (BB*HH*DHH)   // 32768
#define NSL  32            // split-K slices for projections
#define NSPLIT 8           // split-KV factor
#define TSP  (TT/NSPLIT)   // 512 tokens per split

// Scratch (device globals; no allocation allowed)
__device__ float g_qp[NSL][NQ];
__device__ float g_kp[NSL][NQ];
__device__ float g_vp[NSL][NQ];
__device__ float g_q [NQ];             // reduced, pre-scaled
__device__ float g_kn[NQ];
__device__ float g_vn[NQ];
__device__ float g_cp[NSPLIT][NQ];     // unnormalized ctx partials
__device__ float g_ms[NBH][NSPLIT];    // local max
__device__ float g_ss[NBH][NSPLIT];    // local exp-sum
__device__ float g_op[NSL][NQ];

__device__ __forceinline__ float4 ldf4(const float* p) {
    return *reinterpret_cast<const float4*>(p);
}
__device__ __forceinline__ float4 ldf4s(const float* p) {
    return __ldcs(reinterpret_cast<const float4*>(p));   // evict-first stream
}

// ---------------------------------------------------------------------------
// Kernel 1: QKV projection partials, smem-staged weights, 512 threads.
// grid (H=16, NSL=32). Block (h, ds) handles d-slice [ds*32, ds*32+32).
// ---------------------------------------------------------------------------
__global__ void __launch_bounds__(512) qkv_partial(
    const float* __restrict__ x,
    const float* __restrict__ Wq, const float* __restrict__ Wk,
    const float* __restrict__ Wv)
{
    const int h  = blockIdx.x;
    const int ds = blockIdx.y;
    const int tid = threadIdx.x;

    __shared__ float xs[BB][32];
    __shared__ float wsq[32][64];
    __shared__ float wsk[32][64];
    __shared__ float wsv[32][64];

    // stage weight tiles: 512 float4 per matrix, 1 per thread per matrix
    {
        int row = tid >> 4;
        int c4  = (tid & 15) * 4;
        size_t off = (size_t)(ds*32 + row)*1024 + h*DHH + c4;
        *(float4*)&wsq[row][c4] = ldf4(Wq + off);
        *(float4*)&wsk[row][c4] = ldf4(Wk + off);
        *(float4*)&wsv[row][c4] = ldf4(Wv + off);
    }
#pragma unroll
    for (int i = tid; i < BB*32; i += 512) {
        int bb = i >> 5, dd = i & 31;
        xs[bb][dd] = x[bb*DD + ds*32 + dd];
    }
    __syncthreads();

    const int dh = tid & 63;
    const int bg = tid >> 6;          // 0..7, 4 batches each

    float aq[4], ak[4], av[4];
#pragma unroll
    for (int j = 0; j < 4; j++) { aq[j]=0.f; ak[j]=0.f; av[j]=0.f; }

#pragma unroll 8
    for (int d = 0; d < 32; d++) {
        float wq_ = wsq[d][dh];
        float wk_ = wsk[d][dh];
        float wv_ = wsv[d][dh];
#pragma unroll
        for (int j = 0; j < 4; j++) {
            float xv = xs[bg*4 + j][d];
            aq[j] += wq_ * xv;
            ak[j] += wk_ * xv;
            av[j] += wv_ * xv;
        }
    }
#pragma unroll
    for (int j = 0; j < 4; j++) {
        int b = bg*4 + j;
        int o = (b*HH + h)*DHH + dh;
        g_qp[ds][o] = aq[j];
        g_kp[ds][o] = ak[j];
        g_vp[ds][o] = av[j];
    }
}

// ---------------------------------------------------------------------------
// Kernel 1b: reduce QKV partials. grid 128 x 256, slice-parallel.
// ---------------------------------------------------------------------------
__global__ void __launch_bounds__(256) qkv_reduce(
    const float* __restrict__ bq, const float* __restrict__ bk,
    const float* __restrict__ bv)
{
    const int tid = threadIdx.x;
    const int pos = tid & 63;
    const int grp = tid >> 6;
    const int i   = (blockIdx.x * 64 + pos) * 4;

    __shared__ float4 pq[4][64];
    __shared__ float4 pk[4][64];
    __shared__ float4 pv[4][64];

    float4 sq = make_float4(0,0,0,0), sk = sq, sv = sq;
#pragma unroll
    for (int j = 0; j < 8; j++) {
        int s = grp*8 + j;
        float4 a = ldf4(&g_qp[s][i]);
        float4 b2 = ldf4(&g_kp[s][i]);
        float4 c = ldf4(&g_vp[s][i]);
        sq.x += a.x; sq.y += a.y; sq.z += a.z; sq.w += a.w;
        sk.x += b2.x; sk.y += b2.y; sk.z += b2.z; sk.w += b2.w;
        sv.x += c.x; sv.y += c.y; sv.z += c.z; sv.w += c.w;
    }
    pq[grp][pos] = sq; pk[grp][pos] = sk; pv[grp][pos] = sv;
    __syncthreads();

    if (grp == 0) {
        int bi = i & 1023;
        float4 xq = ldf4(bq + bi), xk = ldf4(bk + bi), xv = ldf4(bv + bi);
#pragma unroll
        for (int g = 0; g < 4; g++) {
            float4 a = pq[g][pos], b2 = pk[g][pos], c = pv[g][pos];
            xq.x += a.x; xq.y += a.y; xq.z += a.z; xq.w += a.w;
            xk.x += b2.x; xk.y += b2.y; xk.z += b2.z; xk.w += b2.w;
            xv.x += c.x; xv.y += c.y; xv.z += c.z; xv.w += c.w;
        }
        xq.x *= 0.125f; xq.y *= 0.125f; xq.z *= 0.125f; xq.w *= 0.125f;
        *(float4*)&g_q[i]  = xq;
        *(float4*)&g_kn[i] = xk;
        *(float4*)&g_vn[i] = xv;
    }
}

// ---------------------------------------------------------------------------
// Kernel 2: single-pass online-softmax split-KV attention.
// grid = (B*H, NSPLIT), 256 threads. K/V loads use evict-first hints.
// ---------------------------------------------------------------------------
__global__ void __launch_bounds__(256) attn_split(
    const float* __restrict__ K, const float* __restrict__ V)
{
    const int bh   = blockIdx.x;
    const int sp   = blockIdx.y;
    const int b    = bh >> 4;
    const int h    = bh & 15;
    const int tid  = threadIdx.x;
    const int w    = tid >> 5;
    const int lane = tid & 31;
    const int half = lane >> 4;       // 0 or 1
    const int hl   = lane & 15;       // lane within half
    const int t0 = sp * TSP;

    __shared__ float q_s[DHH];        // pre-scaled by 1/sqrt(DH)
    __shared__ float kn_s[DHH];
    __shared__ float vn_s[DHH];
    __shared__ float mred[8][2];
    __shared__ float lred[8][2];
    __shared__ float vred[8][2][DHH];

    if (tid < DHH) {
        const int i = bh*DHH + tid;
        q_s[tid]  = g_q[i];
        kn_s[tid] = g_kn[i];
        vn_s[tid] = g_vn[i];
    }
    __syncthreads();

    const float4 q4 = ldf4(&q_s[hl*4]);
    const float* kb = K + ((size_t)b*TT*HH + h)*DHH + (size_t)t0*1024;
    const float* vb = V + ((size_t)b*TT*HH + h)*DHH + (size_t)t0*1024;

    float m_run = -1e30f;
    float l_run = 0.f;
    float4 acc = make_float4(0,0,0,0);

    for (int i = 0; i < TSP; i += 128) {
        const int rbase = i + w*16 + half;

        // front-batch all 16 loads before any consume
        float4 kk[8], vv[8];
#pragma unroll
        for (int s = 0; s < 8; s++)
            kk[s] = ldf4s(kb + (size_t)(rbase + 2*s)*1024 + hl*4);
#pragma unroll
        for (int s = 0; s < 8; s++)
            vv[s] = ldf4s(vb + (size_t)(rbase + 2*s)*1024 + hl*4);

        // scores: partial dot per lane, reduce over 16-lane half
        float d[8];
#pragma unroll
        for (int s = 0; s < 8; s++)
            d[s] = kk[s].x*q4.x + kk[s].y*q4.y + kk[s].z*q4.z + kk[s].w*q4.w;
#pragma unroll
        for (int o = 8; o; o >>= 1) {
#pragma unroll
            for (int s = 0; s < 8; s++)
                d[s] += __shfl_xor_sync(0xffffffffu, d[s], o);
        }

        // online softmax update (one rescale per 8 rows)
        float bm = d[0];
#pragma unroll
        for (int s = 1; s < 8; s++) bm = fmaxf(bm, d[s]);
        float nm = fmaxf(m_run, bm);
        float cs = __expf(m_run - nm);
        l_run *= cs;
        acc.x *= cs; acc.y *= cs; acc.z *= cs; acc.w *= cs;
#pragma unroll
        for (int s = 0; s < 8; s++) {
            float p = __expf(d[s] - nm);
            l_run += p;
            acc.x += p*vv[s].x; acc.y += p*vv[s].y;
            acc.z += p*vv[s].z; acc.w += p*vv[s].w;
        }
        m_run = nm;
    }

    // new token (last split, warp 0, half 0)
    if (sp == NSPLIT-1 && w == 0 && lane < 16) {
        float4 kn4 = ldf4(&kn_s[lane*4]);
        float p = kn4.x*q4.x + kn4.y*q4.y + kn4.z*q4.z + kn4.w*q4.w;
#pragma unroll
        for (int o = 8; o; o >>= 1) p += __shfl_xor_sync(0xffffu, p, o);
        float nm = fmaxf(m_run, p);
        float cs = __expf(m_run - nm);
        l_run *= cs;
        acc.x *= cs; acc.y *= cs; acc.z *= cs; acc.w *= cs;
        float pe = __expf(p - nm);
        l_run += pe;
        float4 vn4 = ldf4(&vn_s[lane*4]);
        acc.x += pe*vn4.x; acc.y += pe*vn4.y;
        acc.z += pe*vn4.z; acc.w += pe*vn4.w;
        m_run = nm;
    }

    // stash per-(warp, half) partials
    if (hl == 0) { mred[w][half] = m_run; lred[w][half] = l_run; }
    *(float4*)&vred[w][half][hl*4] = acc;
    __syncthreads();

    // cross-warp combine (64 threads, one per dh)
    if (tid < DHH) {
        float M = -1e30f;
#pragma unroll
        for (int j = 0; j < 8; j++) {
            M = fmaxf(M, mred[j][0]);
            M = fmaxf(M, mred[j][1]);
        }
        float denom = 0.f, s2 = 0.f;
#pragma unroll
        for (int j = 0; j < 8; j++) {
#pragma unroll
            for (int k2 = 0; k2 < 2; k2++) {
                float e = __expf(mred[j][k2] - M);
                denom += e * lred[j][k2];
                s2    += e * vred[j][k2][tid];
            }
        }
        g_cp[sp][bh*DHH + tid] = s2;
        if (tid == 0) { g_ms[bh][sp] = M; g_ss[bh][sp] = denom; }
    }
}

// ---------------------------------------------------------------------------
// Kernel 3: output projection with fused split-combine, smem-staged Wo,
// 512 threads. grid (MC=16, KS=32). k-slice maps to head h = ks/2.
// ---------------------------------------------------------------------------
__global__ void __launch_bounds__(512) out_partial(const float* __restrict__ Wo)
{
    const int mc = blockIdx.x;
    const int ks = blockIdx.y;
    const int tid = threadIdx.x;
    const int h  = ks >> 1;
    const int dhb = (ks & 1) * 32;

    __shared__ float cs[BB][32];
    __shared__ float ws[32][64];
    __shared__ float wgt[NSPLIT][BB];

    // front-batch: ctx partials (2 positions x NSPLIT loads per thread)
    float pv[2][NSPLIT];
#pragma unroll
    for (int it = 0; it < 2; it++) {
        int i = tid + it*512;
        int bb = i >> 5, kk = i & 31;
        int o = (bb*HH + h)*DHH + dhb + kk;
#pragma unroll
        for (int s = 0; s < NSPLIT; s++) pv[it][s] = g_cp[s][o];
    }

    // front-batch: Wo tile (coalesced float4, 1 per thread)
    {
        int row = tid >> 4;
        int c4  = (tid & 15) * 4;
        *(float4*)&ws[row][c4] = ldf4(Wo + (size_t)(ks*32 + row)*1024 + mc*64 + c4);
    }

    // split-combine weights (tid<32); exp chain hides under the loads above
    if (tid < BB) {
        const int bh = tid*HH + h;
        float mv[NSPLIT];
        float M = -1e30f;
#pragma unroll
        for (int s = 0; s < NSPLIT; s++) {
            mv[s] = g_ms[bh][s];
            M = fmaxf(M, mv[s]);
        }
        float e[NSPLIT];
        float denom = 0.f;
#pragma unroll
        for (int s = 0; s < NSPLIT; s++) {
            e[s] = __expf(mv[s] - M);
            denom += e[s] * g_ss[bh][s];
        }
        float inv = 1.0f / denom;
#pragma unroll
        for (int s = 0; s < NSPLIT; s++) wgt[s][tid] = e[s] * inv;
    }
    __syncthreads();

    // combine from registers
#pragma unroll
    for (int it = 0; it < 2; it++) {
        int i = tid + it*512;
        int bb = i >> 5, kk = i & 31;
        float v = 0.f;
#pragma unroll
        for (int s = 0; s < NSPLIT; s++) v += wgt[s][bb]*pv[it][s];
        cs[bb][kk] = v;
    }
    __syncthreads();

    const int m  = tid & 63;
    const int bg = tid >> 6;          // 0..7, 4 batches each

    float acc[4];
#pragma unroll
    for (int j = 0; j < 4; j++) acc[j] = 0.f;

#pragma unroll 8
    for (int k = 0; k < 32; k++) {
        float w_ = ws[k][m];
#pragma unroll
        for (int j = 0; j < 4; j++)
            acc[j] += cs[bg*4 + j][k] * w_;
    }
#pragma unroll
    for (int j = 0; j < 4; j++)
        g_op[ks][(bg*4 + j)*DD + mc*64 + m] = acc[j];
}

// ---------------------------------------------------------------------------
// Kernel 3b: reduce output partials. grid 128 x 256, slice-parallel.
// ---------------------------------------------------------------------------
__global__ void __launch_bounds__(256) out_reduce(
    const float* __restrict__ bo, float* __restrict__ out)
{
    const int tid = threadIdx.x;
    const int pos = tid & 63;
    const int grp = tid >> 6;
    const int i   = (blockIdx.x * 64 + pos) * 4;

    __shared__ float4 ps[4][64];

    float4 s = make_float4(0,0,0,0);
#pragma unroll
    for (int j = 0; j < 8; j++) {
        float4 v = ldf4(&g_op[grp*8 + j][i]);
        s.x += v.x; s.y += v.y; s.z += v.z; s.w += v.w;
    }
    ps[grp][pos] = s;
    __syncthreads();

    if (grp == 0) {
        float4 r = ldf4(bo + (i & 1023));
#pragma unroll
        for (int g = 0; g < 4; g++) {
            float4 v = ps[g][pos];
            r.x += v.x; r.y += v.y; r.z += v.z; r.w += v.w;
        }
        *(float4*)(out + i) = r;
    }
}

// ---------------------------------------------------------------------------
extern "C" void kernel_launch(void* const* d_in, const int* in_sizes, int n_in,
                              void* d_out, int out_size)
{
    const float* x     = (const float*)d_in[0];
    const float* ext_k = (const float*)d_in[1];
    const float* ext_v = (const float*)d_in[2];
    const float* Wq    = (const float*)d_in[3];
    const float* bq    = (const float*)d_in[4];
    const float* Wk    = (const float*)d_in[5];
    const float* bk    = (const float*)d_in[6];
    const float* Wv    = (const float*)d_in[7];
    const float* bv    = (const float*)d_in[8];
    const float* Wo    = (const float*)d_in[9];
    const float* bo    = (const float*)d_in[10];
    // d_in[11] = q_pos (fixed at 4096 by the dataset shapes)

    float* out = (float*)d_out;

    qkv_partial<<<dim3(HH, NSL), 512>>>(x, Wq, Wk, Wv);
    qkv_reduce<<<128, 256>>>(bq, bk, bv);
    attn_split<<<dim3(NBH, NSPLIT), 256>>>(ext_k, ext_v);
    out_partial<<<dim3(16, NSL), 512>>>(Wo);
    out_reduce<<<128, 256>>>(bo, out);
}